// round 12
// baseline (speedup 1.0000x reference)
#include <cuda_runtime.h>
#include <cuda_fp16.h>
#include <cstdint>
#include <math.h>

#define BB 2
#define LL 4096
#define CC 256
#define C2 512
#define QS 768
#define HH 8
#define DD 32
#define KK 9
#define NL 4
#define MS (BB*LL)          /* rows per feature   */
#define M2 (2*MS)           /* batched rows       */
#define MD (BB*LL*KK)       /* points per feature */
#define KVSZ (4*HH*DD*DD)
#define KSSZ (4*HH*DD)

typedef const unsigned int* maskp;

/* ------------------------------------------------------------------ */
/* device globals — feat0 half then feat1 half, contiguous             */
/* ------------------------------------------------------------------ */
__device__ float  g_x[M2*CC];
__device__ __half g_xh[M2*CC];
__device__ float  g_qkv[M2*QS];
__device__ __half g_qkvh[M2*QS];     /* fp16 copy for cross-layer gathers */
__device__ float  g_invn[2*MD];
__device__ __half g_atth[M2*CC];
__device__ __half g_msgh[M2*CC];
__device__ __half g_uh[M2*C2];
__device__ float  g_tb[M2*CC];
__device__ float  g_kvks[KVSZ + KSSZ];
/* per-layer fp16 hi/lo split transposed weights [N,K] */
__device__ __half g_whP[NL*QS*CC], g_wlP[NL*QS*CC];
__device__ __half g_whM[NL*CC*CC], g_wlM[NL*CC*CC];
__device__ __half g_wh1[NL*C2*C2], g_wl1[NL*C2*C2];
__device__ __half g_wh2[NL*CC*C2], g_wl2[NL*CC*C2];

__device__ __forceinline__ float elu1(float x) { return x > 0.f ? x + 1.f : expf(x); }

__device__ __forceinline__ uint32_t smem_u32(const void* p) {
    uint32_t a;
    asm("{ .reg .u64 t; cvta.to.shared.u64 t, %1; cvt.u32.u64 %0, t; }"
        : "=r"(a) : "l"(p));
    return a;
}
__device__ __forceinline__ void cp16(uint32_t dst, const void* src) {
    asm volatile(
        "{ .reg .u64 g; cvta.to.global.u64 g, %1; "
        "cp.async.cg.shared.global [%0], [g], 16; }"
        :: "r"(dst), "l"(src));
}
#define CP_COMMIT() asm volatile("cp.async.commit_group;")
#define CP_WAIT(n)  asm volatile("cp.async.wait_group %0;" :: "n"(n))

__device__ __forceinline__ void ldsm4(uint32_t* r, uint32_t a) {
    asm volatile("ldmatrix.sync.aligned.m8n8.x4.shared.b16 {%0,%1,%2,%3}, [%4];"
                 : "=r"(r[0]), "=r"(r[1]), "=r"(r[2]), "=r"(r[3]) : "r"(a));
}
__device__ __forceinline__ void ldsm2(uint32_t* r, uint32_t a) {
    asm volatile("ldmatrix.sync.aligned.m8n8.x2.shared.b16 {%0,%1}, [%2];"
                 : "=r"(r[0]), "=r"(r[1]) : "r"(a));
}
__device__ __forceinline__ void mma16816(float* c, const uint32_t* a,
                                         const uint32_t* b) {
    asm volatile(
        "mma.sync.aligned.m16n8k16.row.col.f32.f16.f16.f32 "
        "{%0,%1,%2,%3}, {%4,%5,%6,%7}, {%8,%9}, {%0,%1,%2,%3};"
        : "+f"(c[0]), "+f"(c[1]), "+f"(c[2]), "+f"(c[3])
        : "r"(a[0]), "r"(a[1]), "r"(a[2]), "r"(a[3]), "r"(b[0]), "r"(b[1]));
}
__device__ __forceinline__ void hsplit1(float v, __half& h, __half& l) {
    h = __float2half_rn(v);
    l = __float2half_rn(v - __half2float(h));
}

/* ------------------------------------------------------------------ */
/* HMMA GEMM: A fp16 single, W fp16 hi/lo split, cp.async dbl buffer   */
/* CTA 128x128, warp 64x32, k-chunk 32, TSTR=40 conflict-free          */
/* mode bit0: A split across two arrays ([A1|A2], lda=256, Kd=512)     */
/* mode bit1: tanh epilogue + fp16 output (Ch only)                    */
/* mode bit2: write fp32 Cf AND fp16 Ch                                */
/* ------------------------------------------------------------------ */
#define TSTR 40
#define TILE_B (128*TSTR*2)           /* 10240 bytes per tile */
#define OFFB_A  0
#define OFFB_BH (1*TILE_B)
#define OFFB_BL (2*TILE_B)
#define STAGE_B (3*TILE_B)            /* 30720 */
#define DSMEM   (2*STAGE_B)           /* 61440 */

__global__ void __launch_bounds__(256, 2)
hgemm3_kernel(const __half* __restrict__ A1, const __half* __restrict__ A2,
              const __half* __restrict__ Wh, const __half* __restrict__ Wl,
              float* __restrict__ Cf, __half* __restrict__ Ch,
              int N, int Kd, int mode)
{
    extern __shared__ __align__(16) char smh[];
    uint32_t smbase = smem_u32(smh);
    int tid = threadIdx.x, wid = tid >> 5, lane = tid & 31;
    int g = lane >> 2, q = lane & 3;
    int m0 = blockIdx.y << 7, n0 = blockIdx.x << 7;
    int wm = wid >> 2, wn = wid & 3;
    int arow = wm << 6, brow = wn << 5;

    int lr = lane & 7, sel = lane >> 3;
    uint32_t aoff = (uint32_t)(((arow + lr + (sel & 1) * 8) * TSTR
                                + (sel >> 1) * 8) * 2);
    uint32_t boff = (uint32_t)(((brow + lr) * TSTR + (sel & 1) * 8) * 2);

    float acc[4][4][4];
#pragma unroll
    for (int i = 0; i < 4; ++i)
#pragma unroll
        for (int j = 0; j < 4; ++j)
#pragma unroll
            for (int k = 0; k < 4; ++k) acc[i][j][k] = 0.f;

    const int NC = Kd >> 5;

#define ISSUE_CHUNK(CI) do {                                               \
        int k0_ = (CI) << 5;                                               \
        const __half* a_; int lda_, kl_;                                   \
        if (mode & 1) {                                                    \
            if (k0_ < 256) { a_ = A1; kl_ = k0_; }                         \
            else           { a_ = A2; kl_ = k0_ - 256; }                   \
            lda_ = 256;                                                    \
        } else { a_ = A1; kl_ = k0_; lda_ = Kd; }                          \
        uint32_t sb_ = smbase + ((CI) & 1) * STAGE_B;                      \
        _Pragma("unroll")                                                  \
        for (int i_ = 0; i_ < 2; ++i_) {                                   \
            int s_ = tid + (i_ << 8);                                      \
            int row_ = s_ >> 2, part_ = s_ & 3;                            \
            uint32_t dr_ = (uint32_t)(row_ * (TSTR * 2) + part_ * 16);     \
            cp16(sb_ + OFFB_A + dr_,                                       \
                 a_ + (size_t)(m0 + row_) * lda_ + kl_ + part_ * 8);       \
            size_t wsrc_ = (size_t)(n0 + row_) * Kd + k0_ + part_ * 8;     \
            cp16(sb_ + OFFB_BH + dr_, Wh + wsrc_);                         \
            cp16(sb_ + OFFB_BL + dr_, Wl + wsrc_);                         \
        }                                                                  \
        CP_COMMIT();                                                       \
    } while (0)

    ISSUE_CHUNK(0);

    for (int kt = 0; kt < NC; ++kt) {
        if (kt + 1 < NC) { ISSUE_CHUNK(kt + 1); CP_WAIT(1); }
        else             { CP_WAIT(0); }
        __syncthreads();
        uint32_t sb = smbase + (kt & 1) * STAGE_B;
#pragma unroll
        for (int ks = 0; ks < 32; ks += 16) {
            uint32_t aR[4][4], bH[4][2], bL[4][2];
#pragma unroll
            for (int mf = 0; mf < 4; ++mf)
                ldsm4(aR[mf], sb + OFFB_A + aoff + mf * (16 * TSTR * 2) + ks * 2);
#pragma unroll
            for (int nf = 0; nf < 4; ++nf)
                ldsm2(bH[nf], sb + OFFB_BH + boff + nf * (8 * TSTR * 2) + ks * 2);
#pragma unroll
            for (int mf = 0; mf < 4; ++mf)
#pragma unroll
                for (int nf = 0; nf < 4; ++nf)
                    mma16816(acc[mf][nf], aR[mf], bH[nf]);
#pragma unroll
            for (int nf = 0; nf < 4; ++nf)
                ldsm2(bL[nf], sb + OFFB_BL + boff + nf * (8 * TSTR * 2) + ks * 2);
#pragma unroll
            for (int mf = 0; mf < 4; ++mf)
#pragma unroll
                for (int nf = 0; nf < 4; ++nf)
                    mma16816(acc[mf][nf], aR[mf], bL[nf]);
        }
        __syncthreads();
    }
#undef ISSUE_CHUNK

#pragma unroll
    for (int mf = 0; mf < 4; ++mf) {
#pragma unroll
        for (int nf = 0; nf < 4; ++nf) {
            int r = m0 + arow + (mf << 4) + g;
            int c = n0 + brow + (nf << 3) + (q << 1);
            if (mode & 2) {
                float t0 = tanhf(acc[mf][nf][0]), t1 = tanhf(acc[mf][nf][1]);
                float t2 = tanhf(acc[mf][nf][2]), t3 = tanhf(acc[mf][nf][3]);
                *(__half2*)(Ch + (size_t)r * N + c) = __floats2half2_rn(t0, t1);
                *(__half2*)(Ch + (size_t)(r + 8) * N + c) = __floats2half2_rn(t2, t3);
            } else {
                float2 v0, v1;
                v0.x = acc[mf][nf][0]; v0.y = acc[mf][nf][1];
                v1.x = acc[mf][nf][2]; v1.y = acc[mf][nf][3];
                *(float2*)(Cf + (size_t)r * N + c) = v0;
                *(float2*)(Cf + (size_t)(r + 8) * N + c) = v1;
                if (mode & 4) {
                    *(__half2*)(Ch + (size_t)r * N + c) =
                        __floats2half2_rn(v0.x, v0.y);
                    *(__half2*)(Ch + (size_t)(r + 8) * N + c) =
                        __floats2half2_rn(v1.x, v1.y);
                }
            }
        }
    }
}

/* ------------------------------------------------------------------ */
/* weight prep (all layers per launch): transpose + fp16 hi/lo split   */
/* ------------------------------------------------------------------ */
__global__ void wtrans_all_kernel(const float* __restrict__ W,
                                  __half* __restrict__ wh,
                                  __half* __restrict__ wl, int Kd, int N)
{
    int idx = blockIdx.x * 256 + threadIdx.x;
    int per = Kd * N;
    int layer = idx / per, r = idx - layer * per;
    int k = r / N, n = r - k * N;
    float v = W[(size_t)layer * per + (size_t)k * N + n];
    __half h, l; hsplit1(v, h, l);
    size_t dst = (size_t)layer * per + (size_t)n * Kd + k;
    wh[dst] = h; wl[dst] = l;
}

__global__ void wpackT_all_kernel(const float* __restrict__ Wq,
                                  const float* __restrict__ Wk,
                                  const float* __restrict__ Wv,
                                  __half* __restrict__ wh,
                                  __half* __restrict__ wl)
{
    int idx = blockIdx.x * 256 + threadIdx.x;
    int per = CC * QS;
    int layer = idx / per, r = idx - layer * per;
    int k = r / QS, n = r - k * QS;
    const float* src = (n < 256) ? Wq : (n < 512) ? Wk : Wv;
    float v = src[(size_t)layer * CC * CC + (size_t)k * 256 + (n & 255)];
    __half h, l; hsplit1(v, h, l);
    size_t dst = (size_t)layer * (QS * CC) + (size_t)n * CC + k;
    wh[dst] = h; wl[dst] = l;
}

/* initial x copy + fp16 round, both features into contiguous halves   */
__global__ void split_in_kernel(const float* __restrict__ f0,
                                const float* __restrict__ f1,
                                float* __restrict__ x,
                                __half* __restrict__ xh)
{
    int i = blockIdx.x * 256 + threadIdx.x;
    const float* src = (i < MS * CC) ? f0 : f1 - MS * CC;
    float v = src[i];
    x[i] = v;
    xh[i] = __float2half_rn(v);
}

/* ------------------------------------------------------------------ */
/* Self linear attention — batched over 4 slabs (feature x batch)      */
/* ------------------------------------------------------------------ */
__global__ void __launch_bounds__(256) self_kv_kernel(
    const float* __restrict__ qkv, maskp __restrict__ m0p,
    maskp __restrict__ m1p, float* __restrict__ KVKS)
{
    int blk = blockIdx.x;                /* 512 blocks */
    int ch = blk & 15, h = (blk >> 4) & 7, fb = blk >> 7;
    int tid = threadIdx.x;
    int d = tid >> 3, eq = tid & 7, e0 = eq << 2;
    float a0 = 0.f, a1 = 0.f, a2 = 0.f, a3 = 0.f, accs = 0.f;
    int base = (fb << 12) + (ch << 8);
    maskp mp = ((fb >> 1) ? m1p : m0p) + ((fb & 1) << 12) + (ch << 8);
    const float* kp = qkv + (size_t)base * QS + 256 + h * DD + d;
    const float* vp = qkv + (size_t)base * QS + 512 + h * DD + e0;
#pragma unroll 4
    for (int r = 0; r < 256; ++r) {
        float m = mp[r] ? 1.f : 0.f;
        float kf = m * elu1(kp[(size_t)r * QS]);
        float4 v = *(const float4*)(vp + (size_t)r * QS);
        a0 += kf * v.x; a1 += kf * v.y; a2 += kf * v.z; a3 += kf * v.w;
        accs += kf;
    }
    float* kvp = KVKS + ((size_t)((fb * HH + h) * DD + d) * DD + e0);
    atomicAdd(kvp + 0, a0);
    atomicAdd(kvp + 1, a1);
    atomicAdd(kvp + 2, a2);
    atomicAdd(kvp + 3, a3);
    if (eq == 0) atomicAdd(KVKS + KVSZ + (fb * HH + h) * DD + d, accs);
}

__global__ void __launch_bounds__(256) self_att_kernel(
    const float* __restrict__ qkv, const float* __restrict__ KVKS,
    __half* __restrict__ oh)
{
    __shared__ float sKV[HH][DD][DD];
    __shared__ float sKs[HH][DD];
    __shared__ float sQf[8][CC];
    int tid = threadIdx.x;
    int t0 = blockIdx.x << 3;
    int fb = t0 >> 12;
    for (int i = tid; i < HH * DD * DD; i += 256)
        (&sKV[0][0][0])[i] = KVKS[(size_t)fb * HH * DD * DD + i];
    for (int i = tid; i < HH * DD; i += 256)
        (&sKs[0][0])[i] = KVKS[KVSZ + fb * HH * DD + i];
#pragma unroll
    for (int tt = 0; tt < 8; ++tt)
        sQf[tt][tid] = elu1(qkv[(size_t)(t0 + tt) * QS + tid]);
    __syncthreads();
    int h = tid >> 5, e = tid & 31;
#pragma unroll
    for (int tt = 0; tt < 8; ++tt) {
        float den = sQf[tt][(h << 5) + e] * sKs[h][e];
#pragma unroll
        for (int o = 16; o; o >>= 1) den += __shfl_xor_sync(0xffffffffu, den, o);
        float out = 0.f;
#pragma unroll
        for (int d = 0; d < 32; ++d)
            out += sQf[tt][(h << 5) + d] * sKV[h][d][e];
        oh[(size_t)(t0 + tt) * CC + tid] = __float2half_rn(out / (den + 1e-6f));
    }
}

/* ------------------------------------------------------------------ */
/* bilinear taps + invnorm + cross attention (batched, fp16 gathers)   */
/* ------------------------------------------------------------------ */
__device__ __forceinline__ void taps_of(float kx, float ky, int base,
                                        int* r, float* w)
{
    float px = (((kx - 3.5f) / 507.5f * 2.f - 1.f) + 1.f) * 0.5f * 63.f;
    float py = (((ky - 3.5f) / 507.5f * 2.f - 1.f) + 1.f) * 0.5f * 63.f;
    float x0f = floorf(px), y0f = floorf(py);
    float wx = px - x0f, wy = py - y0f;
    int ix0 = min(max((int)x0f, 0), 63);
    int ix1 = min(max((int)x0f + 1, 0), 63);
    int iy0 = min(max((int)y0f, 0), 63);
    int iy1 = min(max((int)y0f + 1, 0), 63);
    r[0] = base + (iy0 << 6) + ix0;
    r[1] = base + (iy0 << 6) + ix1;
    r[2] = base + (iy1 << 6) + ix0;
    r[3] = base + (iy1 << 6) + ix1;
    w[0] = (1.f - wy) * (1.f - wx);
    w[1] = (1.f - wy) * wx;
    w[2] = wy * (1.f - wx);
    w[3] = wy * wx;
}

__global__ void __launch_bounds__(256) invnorm_kernel(
    const __half* __restrict__ xh, const float* __restrict__ kp0,
    const float* __restrict__ kp1, float* __restrict__ invn)
{
    int pg = (blockIdx.x << 3) + (threadIdx.x >> 5);
    int lane = threadIdx.x & 31;
    int f = pg >= MD;
    int pl = pg - f * MD;
    const float* kp = f ? kp1 : kp0;
    int b = pl / (LL * KK);
    int r[4]; float w[4];
    taps_of(kp[(size_t)pl * 2], kp[(size_t)pl * 2 + 1],
            f * MS + b * LL, r, w);
    const __half* f0 = xh + (size_t)r[0] * CC;
    const __half* f1 = xh + (size_t)r[1] * CC;
    const __half* f2 = xh + (size_t)r[2] * CC;
    const __half* f3 = xh + (size_t)r[3] * CC;
    float sq = 0.f;
#pragma unroll
    for (int j = 0; j < 8; ++j) {
        int c = lane + (j << 5);
        float val = w[0]*__half2float(f0[c]) + w[1]*__half2float(f1[c])
                  + w[2]*__half2float(f2[c]) + w[3]*__half2float(f3[c]);
        sq += val * val;
    }
#pragma unroll
    for (int o = 16; o; o >>= 1) sq += __shfl_xor_sync(0xffffffffu, sq, o);
    if (lane == 0) invn[pg] = 1.f / (sqrtf(sq) + 1e-8f);
}

__global__ void __launch_bounds__(256) cross_att_kernel(
    const float* __restrict__ qkv, const __half* __restrict__ qkvh,
    const float* __restrict__ kp0, const float* __restrict__ kp1,
    const float* __restrict__ invn, maskp __restrict__ mc0,
    maskp __restrict__ mc1, __half* __restrict__ oh)
{
    int t = blockIdx.x;
    int tid = threadIdx.x;
    int h = tid >> 5, lane = tid & 31;
    int f = t >> 13;
    int tok = t & (MS - 1);
    int b = tok >> 12;
    const float* kp = f ? kp0 : kp1;
    const float* inv_base = invn + (size_t)(1 - f) * MD;
    maskp mask = f ? mc0 : mc1;
    int src_base = (1 - f) * MS + b * LL;

    __shared__ float sQf[CC];
    __shared__ int   sTap[KK][4];
    __shared__ float sW[KK][4];
    __shared__ float sInv[KK];
    __shared__ float sM[KK];
    sQf[tid] = elu1(qkv[(size_t)t * QS + tid]);
    if (tid < KK) {
        int p = tok * KK + tid;
        int r[4]; float w[4];
        taps_of(kp[(size_t)p * 2], kp[(size_t)p * 2 + 1], src_base, r, w);
#pragma unroll
        for (int i = 0; i < 4; ++i) { sTap[tid][i] = r[i]; sW[tid][i] = w[i]; }
        sInv[tid] = inv_base[p];
        sM[tid] = mask[p] ? 1.f : 0.f;
    }
    __syncthreads();
    int c = (h << 5) + lane;
    float qf = sQf[c];
    float wgt[KK];
    float den = 0.f;
#pragma unroll
    for (int s = 0; s < KK; ++s) {
        float kraw =
            sW[s][0] * __half2float(qkvh[(size_t)sTap[s][0] * QS + 256 + c]) +
            sW[s][1] * __half2float(qkvh[(size_t)sTap[s][1] * QS + 256 + c]) +
            sW[s][2] * __half2float(qkvh[(size_t)sTap[s][2] * QS + 256 + c]) +
            sW[s][3] * __half2float(qkvh[(size_t)sTap[s][3] * QS + 256 + c]);
        float kf = elu1(kraw * sInv[s]) * sM[s];
        float p = qf * kf;
#pragma unroll
        for (int o = 16; o; o >>= 1) p += __shfl_xor_sync(0xffffffffu, p, o);
        wgt[s] = p;
        den += p;
    }
    float inv = 1.f / (den + 1e-6f);
    float out = 0.f;
#pragma unroll
    for (int s = 0; s < KK; ++s) {
        float vraw =
            sW[s][0] * __half2float(qkvh[(size_t)sTap[s][0] * QS + 512 + c]) +
            sW[s][1] * __half2float(qkvh[(size_t)sTap[s][1] * QS + 512 + c]) +
            sW[s][2] * __half2float(qkvh[(size_t)sTap[s][2] * QS + 512 + c]) +
            sW[s][3] * __half2float(qkvh[(size_t)sTap[s][3] * QS + 512 + c]);
        out += wgt[s] * (vraw * sInv[s]);
    }
    oh[(size_t)t * CC + tid] = __float2half_rn(out * inv);
}

/* ------------------------------------------------------------------ */
/* LayerNorm (C=256, eps 1e-5)                                         */
/* ------------------------------------------------------------------ */
__device__ __forceinline__ void ln_core(const float* xr, float* v,
                                        float& mean, float& rstd)
{
    int lane = threadIdx.x & 31;
    float s = 0.f;
#pragma unroll
    for (int j = 0; j < 8; ++j) { v[j] = xr[lane + (j << 5)]; s += v[j]; }
#pragma unroll
    for (int o = 16; o; o >>= 1) s += __shfl_xor_sync(0xffffffffu, s, o);
    mean = s * (1.f / 256.f);
    float q = 0.f;
#pragma unroll
    for (int j = 0; j < 8; ++j) { float d = v[j] - mean; q += d * d; }
#pragma unroll
    for (int o = 16; o; o >>= 1) q += __shfl_xor_sync(0xffffffffu, q, o);
    rstd = rsqrtf(q * (1.f / 256.f) + 1e-5f);
}

__global__ void __launch_bounds__(256) ln_split_kernel(
    const float* __restrict__ X, const float* __restrict__ gam,
    const float* __restrict__ bet, __half* __restrict__ oh)
{
    int warp = threadIdx.x >> 5, lane = threadIdx.x & 31;
    int row = (blockIdx.x << 3) + warp;
    float v[8], mean, rstd;
    ln_core(X + (size_t)row * CC, v, mean, rstd);
#pragma unroll
    for (int j = 0; j < 8; ++j) {
        int c = lane + (j << 5);
        float o = (v[j] - mean) * rstd * gam[c] + bet[c];
        oh[(size_t)row * CC + c] = __float2half_rn(o);
    }
}

__global__ void __launch_bounds__(256) ln_add_kernel(
    const float* __restrict__ X, const float* __restrict__ gam,
    const float* __restrict__ bet, float* __restrict__ x,
    __half* __restrict__ xh)
{
    int warp = threadIdx.x >> 5, lane = threadIdx.x & 31;
    int row = (blockIdx.x << 3) + warp;
    float v[8], mean, rstd;
    ln_core(X + (size_t)row * CC, v, mean, rstd);
#pragma unroll
    for (int j = 0; j < 8; ++j) {
        int c = lane + (j << 5);
        float o = (v[j] - mean) * rstd * gam[c] + bet[c];
        float nx = x[(size_t)row * CC + c] + o;
        x[(size_t)row * CC + c] = nx;
        xh[(size_t)row * CC + c] = __float2half_rn(nx);
    }
}

/* ------------------------------------------------------------------ */
/* host orchestration                                                  */
/* ------------------------------------------------------------------ */
struct LayerW {
    const float *g1, *b1, *g2, *b2;
    __half *whP, *wlP, *whM, *wlM, *wh1, *wl1, *wh2, *wl2;
};
struct Bufs {
    float *t, *kvks;
    __half *atth, *msgh, *uh;
};

static void mlp_tail(float* x, __half* xh, const LayerW& w, const Bufs& s)
{
    hgemm3_kernel<<<dim3(2,128), 256, DSMEM>>>(
        s.atth, (const __half*)0, w.whM, w.wlM, s.t, (__half*)0, CC, CC, 0);
    ln_split_kernel<<<M2/8, 256>>>(s.t, w.g1, w.b1, s.msgh);
    hgemm3_kernel<<<dim3(4,128), 256, DSMEM>>>(
        xh, s.msgh, w.wh1, w.wl1, (float*)0, s.uh, C2, C2, 3);
    hgemm3_kernel<<<dim3(2,128), 256, DSMEM>>>(
        s.uh, (const __half*)0, w.wh2, w.wl2, s.t, (__half*)0, CC, C2, 0);
    ln_add_kernel<<<M2/8, 256>>>(s.t, w.g2, w.b2, x, xh);
}

extern "C" void kernel_launch(void* const* d_in, const int* in_sizes, int n_in,
                              void* d_out, int out_size)
{
    (void)in_sizes; (void)n_in; (void)out_size;
    const float* feat0 = (const float*)d_in[0];
    const float* feat1 = (const float*)d_in[1];
    const float* kp0   = (const float*)d_in[2];
    const float* kp1   = (const float*)d_in[3];
    maskp ms0 = (maskp)d_in[4];
    maskp ms1 = (maskp)d_in[5];
    maskp mc0 = (maskp)d_in[6];
    maskp mc1 = (maskp)d_in[7];
    const float* Wq = (const float*)d_in[8];
    const float* Wk = (const float*)d_in[9];
    const float* Wv = (const float*)d_in[10];
    const float* Wm = (const float*)d_in[11];
    const float* W1 = (const float*)d_in[12];
    const float* W2 = (const float*)d_in[13];
    const float* G1 = (const float*)d_in[14];
    const float* B1 = (const float*)d_in[15];
    const float* G2 = (const float*)d_in[16];
    const float* B2 = (const float*)d_in[17];

    cudaFuncSetAttribute(hgemm3_kernel,
                         cudaFuncAttributeMaxDynamicSharedMemorySize, DSMEM);

    float *px, *pq, *pin;
    __half *pxh, *pqh;
    __half *whP, *wlP, *whM, *wlM, *wh1, *wl1, *wh2, *wl2;
    Bufs s;
    cudaGetSymbolAddress((void**)&px, g_x);
    cudaGetSymbolAddress((void**)&pxh, g_xh);
    cudaGetSymbolAddress((void**)&pq, g_qkv);
    cudaGetSymbolAddress((void**)&pqh, g_qkvh);
    cudaGetSymbolAddress((void**)&pin, g_invn);
    cudaGetSymbolAddress((void**)&s.t, g_tb);
    cudaGetSymbolAddress((void**)&s.kvks, g_kvks);
    cudaGetSymbolAddress((void**)&s.atth, g_atth);
    cudaGetSymbolAddress((void**)&s.msgh, g_msgh);
    cudaGetSymbolAddress((void**)&s.uh, g_uh);
    cudaGetSymbolAddress((void**)&whP, g_whP);
    cudaGetSymbolAddress((void**)&wlP, g_wlP);
    cudaGetSymbolAddress((void**)&whM, g_whM);
    cudaGetSymbolAddress((void**)&wlM, g_wlM);
    cudaGetSymbolAddress((void**)&wh1, g_wh1);
    cudaGetSymbolAddress((void**)&wl1, g_wl1);
    cudaGetSymbolAddress((void**)&wh2, g_wh2);
    cudaGetSymbolAddress((void**)&wl2, g_wl2);

    /* front-loaded weight prep + input round */
    wpackT_all_kernel<<<NL*CC*QS/256, 256>>>(Wq, Wk, Wv, whP, wlP);
    wtrans_all_kernel<<<NL*CC*CC/256, 256>>>(Wm, whM, wlM, CC, CC);
    wtrans_all_kernel<<<NL*C2*C2/256, 256>>>(W1, wh1, wl1, C2, C2);
    wtrans_all_kernel<<<NL*C2*CC/256, 256>>>(W2, wh2, wl2, C2, CC);
    split_in_kernel<<<M2*CC/256, 256>>>(feat0, feat1, px, pxh);

    for (int i = 0; i < 4; ++i) {
        LayerW w;
        w.g1 = G1 + (size_t)i * CC;
        w.b1 = B1 + (size_t)i * CC;
        w.g2 = G2 + (size_t)i * CC;
        w.b2 = B2 + (size_t)i * CC;
        w.whP = whP + (size_t)i * QS * CC; w.wlP = wlP + (size_t)i * QS * CC;
        w.whM = whM + (size_t)i * CC * CC; w.wlM = wlM + (size_t)i * CC * CC;
        w.wh1 = wh1 + (size_t)i * C2 * C2; w.wl1 = wl1 + (size_t)i * C2 * C2;
        w.wh2 = wh2 + (size_t)i * C2 * CC; w.wl2 = wl2 + (size_t)i * C2 * CC;

        if ((i & 1) == 0) {
            /* self layer: plain fp32 qkv */
            hgemm3_kernel<<<dim3(6,128), 256, DSMEM>>>(
                pxh, (const __half*)0, w.whP, w.wlP, pq, (__half*)0,
                QS, CC, 0);
            cudaMemsetAsync(s.kvks, 0, (size_t)(KVSZ + KSSZ) * sizeof(float), 0);
            self_kv_kernel<<<512, 256>>>(pq, ms0, ms1, s.kvks);
            self_att_kernel<<<M2/8, 256>>>(pq, s.kvks, s.atth);
        } else {
            /* cross layer: qkv fp32 + fp16 copy for gathers */
            hgemm3_kernel<<<dim3(6,128), 256, DSMEM>>>(
                pxh, (const __half*)0, w.whP, w.wlP, pq, pqh,
                QS, CC, 4);
            invnorm_kernel<<<2*MD/8, 256>>>(pxh, kp0, kp1, pin);
            cross_att_kernel<<<M2, 256>>>(pq, pqh, kp0, kp1, pin,
                                          mc0, mc1, s.atth);
        }
        mlp_tail(px, pxh, w, s);
    }

    cudaMemcpyAsync(d_out, px, (size_t)M2 * CC * sizeof(float),
                    cudaMemcpyDeviceToDevice, 0);
}

// round 13
// speedup vs baseline: 1.0238x; 1.0238x over previous
#include <cuda_runtime.h>
#include <cuda_fp16.h>
#include <cstdint>
#include <math.h>

#define BB 2
#define LL 4096
#define CC 256
#define C2 512
#define QS 768
#define HH 8
#define DD 32
#define KK 9
#define NL 4
#define MS (BB*LL)          /* rows per feature   */
#define M2 (2*MS)           /* batched rows       */
#define MD (BB*LL*KK)       /* points per feature */
#define KVSZ (4*HH*DD*DD)
#define KSSZ (4*HH*DD)

typedef const unsigned int* maskp;

/* ------------------------------------------------------------------ */
/* device globals — feat0 half then feat1 half, contiguous             */
/* ------------------------------------------------------------------ */
__device__ float  g_x[M2*CC];
__device__ __half g_xh[M2*CC];
__device__ float  g_qkv[M2*QS];
__device__ float  g_invn[2*MD];
__device__ __half g_atth[M2*CC];
__device__ __half g_msgh[M2*CC];
__device__ __half g_uh[M2*C2];
__device__ float  g_tb[M2*CC];
__device__ float  g_kvks[KVSZ + KSSZ];
/* per-layer fp16 hi/lo split transposed weights [N,K] */
__device__ __half g_whP[NL*QS*CC], g_wlP[NL*QS*CC];
__device__ __half g_whM[NL*CC*CC], g_wlM[NL*CC*CC];
__device__ __half g_wh1[NL*C2*C2], g_wl1[NL*C2*C2];
__device__ __half g_wh2[NL*CC*C2], g_wl2[NL*CC*C2];

__device__ __forceinline__ float elu1(float x) { return x > 0.f ? x + 1.f : expf(x); }

__device__ __forceinline__ uint32_t smem_u32(const void* p) {
    uint32_t a;
    asm("{ .reg .u64 t; cvta.to.shared.u64 t, %1; cvt.u32.u64 %0, t; }"
        : "=r"(a) : "l"(p));
    return a;
}
__device__ __forceinline__ void cp16(uint32_t dst, const void* src) {
    asm volatile(
        "{ .reg .u64 g; cvta.to.global.u64 g, %1; "
        "cp.async.cg.shared.global [%0], [g], 16; }"
        :: "r"(dst), "l"(src));
}
#define CP_COMMIT() asm volatile("cp.async.commit_group;")
#define CP_WAIT(n)  asm volatile("cp.async.wait_group %0;" :: "n"(n))

__device__ __forceinline__ void ldsm4(uint32_t* r, uint32_t a) {
    asm volatile("ldmatrix.sync.aligned.m8n8.x4.shared.b16 {%0,%1,%2,%3}, [%4];"
                 : "=r"(r[0]), "=r"(r[1]), "=r"(r[2]), "=r"(r[3]) : "r"(a));
}
__device__ __forceinline__ void mma16816(float* c, const uint32_t* a,
                                         const uint32_t* b) {
    asm volatile(
        "mma.sync.aligned.m16n8k16.row.col.f32.f16.f16.f32 "
        "{%0,%1,%2,%3}, {%4,%5,%6,%7}, {%8,%9}, {%0,%1,%2,%3};"
        : "+f"(c[0]), "+f"(c[1]), "+f"(c[2]), "+f"(c[3])
        : "r"(a[0]), "r"(a[1]), "r"(a[2]), "r"(a[3]), "r"(b[0]), "r"(b[1]));
}
__device__ __forceinline__ void hsplit1(float v, __half& h, __half& l) {
    h = __float2half_rn(v);
    l = __float2half_rn(v - __half2float(h));
}

/* ------------------------------------------------------------------ */
/* HMMA GEMM: A fp16, W fp16 hi/lo split, cp.async dbl buffer          */
/* CTA 128x128, warp 64x32, k-chunk 32, TSTR=40 conflict-free          */
/* B fragments via paired ldsm4 (2 n-tiles per instruction)            */
/* mode bit0: A split across two arrays ([A1|A2], lda=256, Kd=512)     */
/* mode bit1: tanh epilogue + fp16 output (Ch)                         */
/* ------------------------------------------------------------------ */
#define TSTR 40
#define TILE_B (128*TSTR*2)           /* 10240 bytes per tile */
#define OFFB_A  0
#define OFFB_BH (1*TILE_B)
#define OFFB_BL (2*TILE_B)
#define STAGE_B (3*TILE_B)            /* 30720 */
#define DSMEM   (2*STAGE_B)           /* 61440 */

__global__ void __launch_bounds__(256, 2)
hgemm3_kernel(const __half* __restrict__ A1, const __half* __restrict__ A2,
              const __half* __restrict__ Wh, const __half* __restrict__ Wl,
              float* __restrict__ Cf, __half* __restrict__ Ch,
              int N, int Kd, int mode)
{
    extern __shared__ __align__(16) char smh[];
    uint32_t smbase = smem_u32(smh);
    int tid = threadIdx.x, wid = tid >> 5, lane = tid & 31;
    int g = lane >> 2, q = lane & 3;
    int m0 = blockIdx.y << 7, n0 = blockIdx.x << 7;
    int wm = wid >> 2, wn = wid & 3;
    int arow = wm << 6, brow = wn << 5;

    int lr = lane & 7, sel = lane >> 3;
    /* A ldsm4: 16x16 tile (4 8x8 mats: rows lo/hi x k lo/hi) */
    uint32_t aoff = (uint32_t)(((arow + lr + (sel & 1) * 8) * TSTR
                                + (sel >> 1) * 8) * 2);
    /* B paired ldsm4: mats = nf k-lo, nf k-hi, nf+1 k-lo, nf+1 k-hi */
    uint32_t boff4 = (uint32_t)(((brow + (sel >> 1) * 8 + lr) * TSTR
                                 + (sel & 1) * 8) * 2);

    float acc[4][4][4];
#pragma unroll
    for (int i = 0; i < 4; ++i)
#pragma unroll
        for (int j = 0; j < 4; ++j)
#pragma unroll
            for (int k = 0; k < 4; ++k) acc[i][j][k] = 0.f;

    const int NC = Kd >> 5;

#define ISSUE_CHUNK(CI) do {                                               \
        int k0_ = (CI) << 5;                                               \
        const __half* a_; int lda_, kl_;                                   \
        if (mode & 1) {                                                    \
            if (k0_ < 256) { a_ = A1; kl_ = k0_; }                         \
            else           { a_ = A2; kl_ = k0_ - 256; }                   \
            lda_ = 256;                                                    \
        } else { a_ = A1; kl_ = k0_; lda_ = Kd; }                          \
        uint32_t sb_ = smbase + ((CI) & 1) * STAGE_B;                      \
        _Pragma("unroll")                                                  \
        for (int i_ = 0; i_ < 2; ++i_) {                                   \
            int s_ = tid + (i_ << 8);                                      \
            int row_ = s_ >> 2, part_ = s_ & 3;                            \
            uint32_t dr_ = (uint32_t)(row_ * (TSTR * 2) + part_ * 16);     \
            cp16(sb_ + OFFB_A + dr_,                                       \
                 a_ + (size_t)(m0 + row_) * lda_ + kl_ + part_ * 8);       \
            size_t wsrc_ = (size_t)(n0 + row_) * Kd + k0_ + part_ * 8;     \
            cp16(sb_ + OFFB_BH + dr_, Wh + wsrc_);                         \
            cp16(sb_ + OFFB_BL + dr_, Wl + wsrc_);                         \
        }                                                                  \
        CP_COMMIT();                                                       \
    } while (0)

    ISSUE_CHUNK(0);

    for (int kt = 0; kt < NC; ++kt) {
        if (kt + 1 < NC) { ISSUE_CHUNK(kt + 1); CP_WAIT(1); }
        else             { CP_WAIT(0); }
        __syncthreads();
        uint32_t sb = smbase + (kt & 1) * STAGE_B;
#pragma unroll
        for (int ks = 0; ks < 32; ks += 16) {
            uint32_t aR[4][4], bH[2][4], bL[2][4];
#pragma unroll
            for (int mf = 0; mf < 4; ++mf)
                ldsm4(aR[mf], sb + OFFB_A + aoff + mf * (16 * TSTR * 2) + ks * 2);
#pragma unroll
            for (int p = 0; p < 2; ++p)
                ldsm4(bH[p], sb + OFFB_BH + boff4 + p * (16 * TSTR * 2) + ks * 2);
#pragma unroll
            for (int mf = 0; mf < 4; ++mf)
#pragma unroll
                for (int nf = 0; nf < 4; ++nf)
                    mma16816(acc[mf][nf], aR[mf], &bH[nf >> 1][(nf & 1) << 1]);
#pragma unroll
            for (int p = 0; p < 2; ++p)
                ldsm4(bL[p], sb + OFFB_BL + boff4 + p * (16 * TSTR * 2) + ks * 2);
#pragma unroll
            for (int mf = 0; mf < 4; ++mf)
#pragma unroll
                for (int nf = 0; nf < 4; ++nf)
                    mma16816(acc[mf][nf], aR[mf], &bL[nf >> 1][(nf & 1) << 1]);
        }
        __syncthreads();
    }
#undef ISSUE_CHUNK

#pragma unroll
    for (int mf = 0; mf < 4; ++mf) {
#pragma unroll
        for (int nf = 0; nf < 4; ++nf) {
            int r = m0 + arow + (mf << 4) + g;
            int c = n0 + brow + (nf << 3) + (q << 1);
            if (mode & 2) {
                float t0 = tanhf(acc[mf][nf][0]), t1 = tanhf(acc[mf][nf][1]);
                float t2 = tanhf(acc[mf][nf][2]), t3 = tanhf(acc[mf][nf][3]);
                *(__half2*)(Ch + (size_t)r * N + c) = __floats2half2_rn(t0, t1);
                *(__half2*)(Ch + (size_t)(r + 8) * N + c) = __floats2half2_rn(t2, t3);
            } else {
                float2 v0, v1;
                v0.x = acc[mf][nf][0]; v0.y = acc[mf][nf][1];
                v1.x = acc[mf][nf][2]; v1.y = acc[mf][nf][3];
                *(float2*)(Cf + (size_t)r * N + c) = v0;
                *(float2*)(Cf + (size_t)(r + 8) * N + c) = v1;
            }
        }
    }
}

/* ------------------------------------------------------------------ */
/* weight prep (all layers per launch): transpose + fp16 hi/lo split   */
/* ------------------------------------------------------------------ */
__global__ void wtrans_all_kernel(const float* __restrict__ W,
                                  __half* __restrict__ wh,
                                  __half* __restrict__ wl, int Kd, int N)
{
    int idx = blockIdx.x * 256 + threadIdx.x;
    int per = Kd * N;
    int layer = idx / per, r = idx - layer * per;
    int k = r / N, n = r - k * N;
    float v = W[(size_t)layer * per + (size_t)k * N + n];
    __half h, l; hsplit1(v, h, l);
    size_t dst = (size_t)layer * per + (size_t)n * Kd + k;
    wh[dst] = h; wl[dst] = l;
}

__global__ void wpackT_all_kernel(const float* __restrict__ Wq,
                                  const float* __restrict__ Wk,
                                  const float* __restrict__ Wv,
                                  __half* __restrict__ wh,
                                  __half* __restrict__ wl)
{
    int idx = blockIdx.x * 256 + threadIdx.x;
    int per = CC * QS;
    int layer = idx / per, r = idx - layer * per;
    int k = r / QS, n = r - k * QS;
    const float* src = (n < 256) ? Wq : (n < 512) ? Wk : Wv;
    float v = src[(size_t)layer * CC * CC + (size_t)k * 256 + (n & 255)];
    __half h, l; hsplit1(v, h, l);
    size_t dst = (size_t)layer * (QS * CC) + (size_t)n * CC + k;
    wh[dst] = h; wl[dst] = l;
}

/* initial x copy + fp16 round, both features into contiguous halves   */
__global__ void split_in_kernel(const float* __restrict__ f0,
                                const float* __restrict__ f1,
                                float* __restrict__ x,
                                __half* __restrict__ xh)
{
    int i = blockIdx.x * 256 + threadIdx.x;
    const float* src = (i < MS * CC) ? f0 : f1 - MS * CC;
    float v = src[i];
    x[i] = v;
    xh[i] = __float2half_rn(v);
}

/* ------------------------------------------------------------------ */
/* Self linear attention — batched over 4 slabs (feature x batch)      */
/* ------------------------------------------------------------------ */
__global__ void __launch_bounds__(256) self_kv_kernel(
    const float* __restrict__ qkv, maskp __restrict__ m0p,
    maskp __restrict__ m1p, float* __restrict__ KVKS)
{
    int blk = blockIdx.x;                /* 512 blocks */
    int ch = blk & 15, h = (blk >> 4) & 7, fb = blk >> 7;
    int tid = threadIdx.x;
    int d = tid >> 3, eq = tid & 7, e0 = eq << 2;
    float a0 = 0.f, a1 = 0.f, a2 = 0.f, a3 = 0.f, accs = 0.f;
    int base = (fb << 12) + (ch << 8);
    maskp mp = ((fb >> 1) ? m1p : m0p) + ((fb & 1) << 12) + (ch << 8);
    const float* kp = qkv + (size_t)base * QS + 256 + h * DD + d;
    const float* vp = qkv + (size_t)base * QS + 512 + h * DD + e0;
#pragma unroll 4
    for (int r = 0; r < 256; ++r) {
        float m = mp[r] ? 1.f : 0.f;
        float kf = m * elu1(kp[(size_t)r * QS]);
        float4 v = *(const float4*)(vp + (size_t)r * QS);
        a0 += kf * v.x; a1 += kf * v.y; a2 += kf * v.z; a3 += kf * v.w;
        accs += kf;
    }
    float* kvp = KVKS + ((size_t)((fb * HH + h) * DD + d) * DD + e0);
    atomicAdd(kvp + 0, a0);
    atomicAdd(kvp + 1, a1);
    atomicAdd(kvp + 2, a2);
    atomicAdd(kvp + 3, a3);
    if (eq == 0) atomicAdd(KVKS + KVSZ + (fb * HH + h) * DD + d, accs);
}

__global__ void __launch_bounds__(256) self_att_kernel(
    const float* __restrict__ qkv, const float* __restrict__ KVKS,
    __half* __restrict__ oh)
{
    __shared__ float sKV[HH][DD][DD];
    __shared__ float sKs[HH][DD];
    __shared__ float sQf[8][CC];
    int tid = threadIdx.x;
    int t0 = blockIdx.x << 3;
    int fb = t0 >> 12;
    for (int i = tid; i < HH * DD * DD; i += 256)
        (&sKV[0][0][0])[i] = KVKS[(size_t)fb * HH * DD * DD + i];
    for (int i = tid; i < HH * DD; i += 256)
        (&sKs[0][0])[i] = KVKS[KVSZ + fb * HH * DD + i];
#pragma unroll
    for (int tt = 0; tt < 8; ++tt)
        sQf[tt][tid] = elu1(qkv[(size_t)(t0 + tt) * QS + tid]);
    __syncthreads();
    int h = tid >> 5, e = tid & 31;
#pragma unroll
    for (int tt = 0; tt < 8; ++tt) {
        float den = sQf[tt][(h << 5) + e] * sKs[h][e];
#pragma unroll
        for (int o = 16; o; o >>= 1) den += __shfl_xor_sync(0xffffffffu, den, o);
        float out = 0.f;
#pragma unroll
        for (int d = 0; d < 32; ++d)
            out += sQf[tt][(h << 5) + d] * sKV[h][d][e];
        oh[(size_t)(t0 + tt) * CC + tid] = __float2half_rn(out / (den + 1e-6f));
    }
}

/* ------------------------------------------------------------------ */
/* bilinear taps + invnorm + cross attention (batched, fp32 gathers)   */
/* ------------------------------------------------------------------ */
__device__ __forceinline__ void taps_of(float kx, float ky, int base,
                                        int* r, float* w)
{
    float px = (((kx - 3.5f) / 507.5f * 2.f - 1.f) + 1.f) * 0.5f * 63.f;
    float py = (((ky - 3.5f) / 507.5f * 2.f - 1.f) + 1.f) * 0.5f * 63.f;
    float x0f = floorf(px), y0f = floorf(py);
    float wx = px - x0f, wy = py - y0f;
    int ix0 = min(max((int)x0f, 0), 63);
    int ix1 = min(max((int)x0f + 1, 0), 63);
    int iy0 = min(max((int)y0f, 0), 63);
    int iy1 = min(max((int)y0f + 1, 0), 63);
    r[0] = base + (iy0 << 6) + ix0;
    r[1] = base + (iy0 << 6) + ix1;
    r[2] = base + (iy1 << 6) + ix0;
    r[3] = base + (iy1 << 6) + ix1;
    w[0] = (1.f - wy) * (1.f - wx);
    w[1] = (1.f - wy) * wx;
    w[2] = wy * (1.f - wx);
    w[3] = wy * wx;
}

__global__ void __launch_bounds__(256) invnorm_kernel(
    const float* __restrict__ x, const float* __restrict__ kp0,
    const float* __restrict__ kp1, float* __restrict__ invn)
{
    int pg = (blockIdx.x << 3) + (threadIdx.x >> 5);
    int lane = threadIdx.x & 31;
    int f = pg >= MD;
    int pl = pg - f * MD;
    const float* kp = f ? kp1 : kp0;
    int b = pl / (LL * KK);
    int r[4]; float w[4];
    taps_of(kp[(size_t)pl * 2], kp[(size_t)pl * 2 + 1],
            f * MS + b * LL, r, w);
    const float* f0 = x + (size_t)r[0] * CC;
    const float* f1 = x + (size_t)r[1] * CC;
    const float* f2 = x + (size_t)r[2] * CC;
    const float* f3 = x + (size_t)r[3] * CC;
    float sq = 0.f;
#pragma unroll
    for (int j = 0; j < 8; ++j) {
        int c = lane + (j << 5);
        float val = w[0]*f0[c] + w[1]*f1[c] + w[2]*f2[c] + w[3]*f3[c];
        sq += val * val;
    }
#pragma unroll
    for (int o = 16; o; o >>= 1) sq += __shfl_xor_sync(0xffffffffu, sq, o);
    if (lane == 0) invn[pg] = 1.f / (sqrtf(sq) + 1e-8f);
}

__global__ void __launch_bounds__(256) cross_att_kernel(
    const float* __restrict__ qkv, const float* __restrict__ kp0,
    const float* __restrict__ kp1, const float* __restrict__ invn,
    maskp __restrict__ mc0, maskp __restrict__ mc1,
    __half* __restrict__ oh)
{
    int t = blockIdx.x;
    int tid = threadIdx.x;
    int h = tid >> 5, lane = tid & 31;
    int f = t >> 13;
    int tok = t & (MS - 1);
    int b = tok >> 12;
    const float* kp = f ? kp0 : kp1;
    const float* inv_base = invn + (size_t)(1 - f) * MD;
    maskp mask = f ? mc0 : mc1;
    int src_base = (1 - f) * MS + b * LL;

    __shared__ float sQf[CC];
    __shared__ int   sTap[KK][4];
    __shared__ float sW[KK][4];
    __shared__ float sInv[KK];
    __shared__ float sM[KK];
    sQf[tid] = elu1(qkv[(size_t)t * QS + tid]);
    if (tid < KK) {
        int p = tok * KK + tid;
        int r[4]; float w[4];
        taps_of(kp[(size_t)p * 2], kp[(size_t)p * 2 + 1], src_base, r, w);
#pragma unroll
        for (int i = 0; i < 4; ++i) { sTap[tid][i] = r[i]; sW[tid][i] = w[i]; }
        sInv[tid] = inv_base[p];
        sM[tid] = mask[p] ? 1.f : 0.f;
    }
    __syncthreads();
    int c = (h << 5) + lane;
    float qf = sQf[c];
    float wgt[KK];
    float den = 0.f;
#pragma unroll
    for (int s = 0; s < KK; ++s) {
        float kraw =
            sW[s][0] * qkv[(size_t)sTap[s][0] * QS + 256 + c] +
            sW[s][1] * qkv[(size_t)sTap[s][1] * QS + 256 + c] +
            sW[s][2] * qkv[(size_t)sTap[s][2] * QS + 256 + c] +
            sW[s][3] * qkv[(size_t)sTap[s][3] * QS + 256 + c];
        float kf = elu1(kraw * sInv[s]) * sM[s];
        float p = qf * kf;
#pragma unroll
        for (int o = 16; o; o >>= 1) p += __shfl_xor_sync(0xffffffffu, p, o);
        wgt[s] = p;
        den += p;
    }
    float inv = 1.f / (den + 1e-6f);
    float out = 0.f;
#pragma unroll
    for (int s = 0; s < KK; ++s) {
        float vraw =
            sW[s][0] * qkv[(size_t)sTap[s][0] * QS + 512 + c] +
            sW[s][1] * qkv[(size_t)sTap[s][1] * QS + 512 + c] +
            sW[s][2] * qkv[(size_t)sTap[s][2] * QS + 512 + c] +
            sW[s][3] * qkv[(size_t)sTap[s][3] * QS + 512 + c];
        out += wgt[s] * (vraw * sInv[s]);
    }
    oh[(size_t)t * CC + tid] = __float2half_rn(out * inv);
}

/* ------------------------------------------------------------------ */
/* LayerNorm (C=256, eps 1e-5)                                         */
/* ------------------------------------------------------------------ */
__device__ __forceinline__ void ln_core(const float* xr, float* v,
                                        float& mean, float& rstd)
{
    int lane = threadIdx.x & 31;
    float s = 0.f;
#pragma unroll
    for (int j = 0; j < 8; ++j) { v[j] = xr[lane + (j << 5)]; s += v[j]; }
#pragma unroll
    for (int o = 16; o; o >>= 1) s += __shfl_xor_sync(0xffffffffu, s, o);
    mean = s * (1.f / 256.f);
    float q = 0.f;
#pragma unroll
    for (int j = 0; j < 8; ++j) { float d = v[j] - mean; q += d * d; }
#pragma unroll
    for (int o = 16; o; o >>= 1) q += __shfl_xor_sync(0xffffffffu, q, o);
    rstd = rsqrtf(q * (1.f / 256.f) + 1e-5f);
}

__global__ void __launch_bounds__(256) ln_split_kernel(
    const float* __restrict__ X, const float* __restrict__ gam,
    const float* __restrict__ bet, __half* __restrict__ oh)
{
    int warp = threadIdx.x >> 5, lane = threadIdx.x & 31;
    int row = (blockIdx.x << 3) + warp;
    float v[8], mean, rstd;
    ln_core(X + (size_t)row * CC, v, mean, rstd);
#pragma unroll
    for (int j = 0; j < 8; ++j) {
        int c = lane + (j << 5);
        float o = (v[j] - mean) * rstd * gam[c] + bet[c];
        oh[(size_t)row * CC + c] = __float2half_rn(o);
    }
}

__global__ void __launch_bounds__(256) ln_add_kernel(
    const float* __restrict__ X, const float* __restrict__ gam,
    const float* __restrict__ bet, float* __restrict__ x,
    __half* __restrict__ xh)
{
    int warp = threadIdx.x >> 5, lane = threadIdx.x & 31;
    int row = (blockIdx.x << 3) + warp;
    float v[8], mean, rstd;
    ln_core(X + (size_t)row * CC, v, mean, rstd);
#pragma unroll
    for (int j = 0; j < 8; ++j) {
        int c = lane + (j << 5);
        float o = (v[j] - mean) * rstd * gam[c] + bet[c];
        float nx = x[(size_t)row * CC + c] + o;
        x[(size_t)row * CC + c] = nx;
        xh[(size_t)row * CC + c] = __float2half_rn(nx);
    }
}

/* ------------------------------------------------------------------ */
/* host orchestration                                                  */
/* ------------------------------------------------------------------ */
struct LayerW {
    const float *g1, *b1, *g2, *b2;
    __half *whP, *wlP, *whM, *wlM, *wh1, *wl1, *wh2, *wl2;
};
struct Bufs {
    float *t, *kvks;
    __half *atth, *msgh, *uh;
};

static void mlp_tail(float* x, __half* xh, const LayerW& w, const Bufs& s)
{
    hgemm3_kernel<<<dim3(2,128), 256, DSMEM>>>(
        s.atth, (const __half*)0, w.whM, w.wlM, s.t, (__half*)0, CC, CC, 0);
    ln_split_kernel<<<M2/8, 256>>>(s.t, w.g1, w.b1, s.msgh);
    hgemm3_kernel<<<dim3(4,128), 256, DSMEM>>>(
        xh, s.msgh, w.wh1, w.wl1, (float*)0, s.uh, C2, C2, 3);
    hgemm3_kernel<<<dim3(2,128), 256, DSMEM>>>(
        s.uh, (const __half*)0, w.wh2, w.wl2, s.t, (__half*)0, CC, C2, 0);
    ln_add_kernel<<<M2/8, 256>>>(s.t, w.g2, w.b2, x, xh);
}

extern "C" void kernel_launch(void* const* d_in, const int* in_sizes, int n_in,
                              void* d_out, int out_size)
{
    (void)in_sizes; (void)n_in; (void)out_size;
    const float* feat0 = (const float*)d_in[0];
    const float* feat1 = (const float*)d_in[1];
    const float* kp0   = (const float*)d_in[2];
    const float* kp1   = (const float*)d_in[3];
    maskp ms0 = (maskp)d_in[4];
    maskp ms1 = (maskp)d_in[5];
    maskp mc0 = (maskp)d_in[6];
    maskp mc1 = (maskp)d_in[7];
    const float* Wq = (const float*)d_in[8];
    const float* Wk = (const float*)d_in[9];
    const float* Wv = (const float*)d_in[10];
    const float* Wm = (const float*)d_in[11];
    const float* W1 = (const float*)d_in[12];
    const float* W2 = (const float*)d_in[13];
    const float* G1 = (const float*)d_in[14];
    const float* B1 = (const float*)d_in[15];
    const float* G2 = (const float*)d_in[16];
    const float* B2 = (const float*)d_in[17];

    cudaFuncSetAttribute(hgemm3_kernel,
                         cudaFuncAttributeMaxDynamicSharedMemorySize, DSMEM);

    float *px, *pq, *pin;
    __half *pxh;
    __half *whP, *wlP, *whM, *wlM, *wh1, *wl1, *wh2, *wl2;
    Bufs s;
    cudaGetSymbolAddress((void**)&px, g_x);
    cudaGetSymbolAddress((void**)&pxh, g_xh);
    cudaGetSymbolAddress((void**)&pq, g_qkv);
    cudaGetSymbolAddress((void**)&pin, g_invn);
    cudaGetSymbolAddress((void**)&s.t, g_tb);
    cudaGetSymbolAddress((void**)&s.kvks, g_kvks);
    cudaGetSymbolAddress((void**)&s.atth, g_atth);
    cudaGetSymbolAddress((void**)&s.msgh, g_msgh);
    cudaGetSymbolAddress((void**)&s.uh, g_uh);
    cudaGetSymbolAddress((void**)&whP, g_whP);
    cudaGetSymbolAddress((void**)&wlP, g_wlP);
    cudaGetSymbolAddress((void**)&whM, g_whM);
    cudaGetSymbolAddress((void**)&wlM, g_wlM);
    cudaGetSymbolAddress((void**)&wh1, g_wh1);
    cudaGetSymbolAddress((void**)&wl1, g_wl1);
    cudaGetSymbolAddress((void**)&wh2, g_wh2);
    cudaGetSymbolAddress((void**)&wl2, g_wl2);

    /* front-loaded weight prep + input round */
    wpackT_all_kernel<<<NL*CC*QS/256, 256>>>(Wq, Wk, Wv, whP, wlP);
    wtrans_all_kernel<<<NL*CC*CC/256, 256>>>(Wm, whM, wlM, CC, CC);
    wtrans_all_kernel<<<NL*C2*C2/256, 256>>>(W1, wh1, wl1, C2, C2);
    wtrans_all_kernel<<<NL*C2*CC/256, 256>>>(W2, wh2, wl2, C2, CC);
    split_in_kernel<<<M2*CC/256, 256>>>(feat0, feat1, px, pxh);

    for (int i = 0; i < 4; ++i) {
        LayerW w;
        w.g1 = G1 + (size_t)i * CC;
        w.b1 = B1 + (size_t)i * CC;
        w.g2 = G2 + (size_t)i * CC;
        w.b2 = B2 + (size_t)i * CC;
        w.whP = whP + (size_t)i * QS * CC; w.wlP = wlP + (size_t)i * QS * CC;
        w.whM = whM + (size_t)i * CC * CC; w.wlM = wlM + (size_t)i * CC * CC;
        w.wh1 = wh1 + (size_t)i * C2 * C2; w.wl1 = wl1 + (size_t)i * C2 * C2;
        w.wh2 = wh2 + (size_t)i * C2 * CC; w.wl2 = wl2 + (size_t)i * C2 * CC;

        hgemm3_kernel<<<dim3(6,128), 256, DSMEM>>>(
            pxh, (const __half*)0, w.whP, w.wlP, pq, (__half*)0, QS, CC, 0);

        if ((i & 1) == 0) {
            cudaMemsetAsync(s.kvks, 0, (size_t)(KVSZ + KSSZ) * sizeof(float), 0);
            self_kv_kernel<<<512, 256>>>(pq, ms0, ms1, s.kvks);
            self_att_kernel<<<M2/8, 256>>>(pq, s.kvks, s.atth);
        } else {
            invnorm_kernel<<<2*MD/8, 256>>>(px, kp0, kp1, pin);
            cross_att_kernel<<<M2, 256>>>(pq, kp0, kp1, pin, mc0, mc1, s.atth);
        }
        mlp_tail(px, pxh, w, s);
    }

    cudaMemcpyAsync(d_out, px, (size_t)M2 * CC * sizeof(float),
                    cudaMemcpyDeviceToDevice, 0);
}

// round 14
// speedup vs baseline: 1.2045x; 1.1765x over previous
#include <cuda_runtime.h>
#include <cuda_fp16.h>
#include <cstdint>
#include <math.h>

#define BB 2
#define LL 4096
#define CC 256
#define C2 512
#define QS 768
#define HH 8
#define DD 32
#define KK 9
#define NL 4
#define MS (BB*LL)          /* rows per feature   */
#define M2 (2*MS)           /* batched rows       */
#define MD (BB*LL*KK)       /* points per feature */
#define KVSZ (4*HH*DD*DD)
#define KSSZ (4*HH*DD)

typedef const unsigned int* maskp;

/* ------------------------------------------------------------------ */
/* device globals — feat0 half then feat1 half, contiguous             */
/* ------------------------------------------------------------------ */
__device__ float  g_x[M2*CC];
__device__ __half g_xh[M2*CC];
__device__ float  g_qkv[M2*QS];
__device__ float  g_invn[2*MD];
__device__ __half g_atth[M2*CC];
__device__ __half g_msgh[M2*CC];
__device__ __half g_uh[M2*C2];
__device__ float  g_tb[M2*CC];
__device__ float  g_kvks[KVSZ + KSSZ];
/* per-layer fp16 transposed weights [N,K] */
__device__ __half g_whP[NL*QS*CC];
__device__ __half g_whM[NL*CC*CC];
__device__ __half g_wh1[NL*C2*C2];
__device__ __half g_wh2[NL*CC*C2];

__device__ __forceinline__ float elu1(float x) { return x > 0.f ? x + 1.f : expf(x); }

__device__ __forceinline__ uint32_t smem_u32(const void* p) {
    uint32_t a;
    asm("{ .reg .u64 t; cvta.to.shared.u64 t, %1; cvt.u32.u64 %0, t; }"
        : "=r"(a) : "l"(p));
    return a;
}
__device__ __forceinline__ void cp16(uint32_t dst, const void* src) {
    asm volatile(
        "{ .reg .u64 g; cvta.to.global.u64 g, %1; "
        "cp.async.cg.shared.global [%0], [g], 16; }"
        :: "r"(dst), "l"(src));
}
#define CP_COMMIT() asm volatile("cp.async.commit_group;")
#define CP_WAIT(n)  asm volatile("cp.async.wait_group %0;" :: "n"(n))

__device__ __forceinline__ void ldsm4(uint32_t* r, uint32_t a) {
    asm volatile("ldmatrix.sync.aligned.m8n8.x4.shared.b16 {%0,%1,%2,%3}, [%4];"
                 : "=r"(r[0]), "=r"(r[1]), "=r"(r[2]), "=r"(r[3]) : "r"(a));
}
__device__ __forceinline__ void mma16816(float* c, const uint32_t* a,
                                         const uint32_t* b) {
    asm volatile(
        "mma.sync.aligned.m16n8k16.row.col.f32.f16.f16.f32 "
        "{%0,%1,%2,%3}, {%4,%5,%6,%7}, {%8,%9}, {%0,%1,%2,%3};"
        : "+f"(c[0]), "+f"(c[1]), "+f"(c[2]), "+f"(c[3])
        : "r"(a[0]), "r"(a[1]), "r"(a[2]), "r"(a[3]), "r"(b[0]), "r"(b[1]));
}

/* ------------------------------------------------------------------ */
/* HMMA GEMM: A fp16, W fp16 (single), cp.async dbl buffer             */
/* CTA 128x128, warp 64x32, k-chunk 32, TSTR=40 conflict-free          */
/* B fragments via paired ldsm4 (2 n-tiles per instruction)            */
/* mode bit0: A split across two arrays ([A1|A2], lda=256, Kd=512)     */
/* mode bit1: tanh epilogue + fp16 output (Ch)                         */
/* ------------------------------------------------------------------ */
#define TSTR 40
#define TILE_B (128*TSTR*2)           /* 10240 bytes per tile */
#define OFFB_A  0
#define OFFB_BH (1*TILE_B)
#define STAGE_B (2*TILE_B)            /* 20480 */
#define DSMEM   (2*STAGE_B)           /* 40960 */

__global__ void __launch_bounds__(256, 2)
hgemm4_kernel(const __half* __restrict__ A1, const __half* __restrict__ A2,
              const __half* __restrict__ Wh,
              float* __restrict__ Cf, __half* __restrict__ Ch,
              int N, int Kd, int mode)
{
    extern __shared__ __align__(16) char smh[];
    uint32_t smbase = smem_u32(smh);
    int tid = threadIdx.x, wid = tid >> 5, lane = tid & 31;
    int g = lane >> 2, q = lane & 3;
    int m0 = blockIdx.y << 7, n0 = blockIdx.x << 7;
    int wm = wid >> 2, wn = wid & 3;
    int arow = wm << 6, brow = wn << 5;

    int lr = lane & 7, sel = lane >> 3;
    /* A ldsm4: 16x16 tile */
    uint32_t aoff = (uint32_t)(((arow + lr + (sel & 1) * 8) * TSTR
                                + (sel >> 1) * 8) * 2);
    /* B paired ldsm4: mats = nf k-lo, nf k-hi, nf+1 k-lo, nf+1 k-hi */
    uint32_t boff4 = (uint32_t)(((brow + (sel >> 1) * 8 + lr) * TSTR
                                 + (sel & 1) * 8) * 2);

    float acc[4][4][4];
#pragma unroll
    for (int i = 0; i < 4; ++i)
#pragma unroll
        for (int j = 0; j < 4; ++j)
#pragma unroll
            for (int k = 0; k < 4; ++k) acc[i][j][k] = 0.f;

    const int NC = Kd >> 5;

#define ISSUE_CHUNK(CI) do {                                               \
        int k0_ = (CI) << 5;                                               \
        const __half* a_; int lda_, kl_;                                   \
        if (mode & 1) {                                                    \
            if (k0_ < 256) { a_ = A1; kl_ = k0_; }                         \
            else           { a_ = A2; kl_ = k0_ - 256; }                   \
            lda_ = 256;                                                    \
        } else { a_ = A1; kl_ = k0_; lda_ = Kd; }                          \
        uint32_t sb_ = smbase + ((CI) & 1) * STAGE_B;                      \
        _Pragma("unroll")                                                  \
        for (int i_ = 0; i_ < 2; ++i_) {                                   \
            int s_ = tid + (i_ << 8);                                      \
            int row_ = s_ >> 2, part_ = s_ & 3;                            \
            uint32_t dr_ = (uint32_t)(row_ * (TSTR * 2) + part_ * 16);     \
            cp16(sb_ + OFFB_A + dr_,                                       \
                 a_ + (size_t)(m0 + row_) * lda_ + kl_ + part_ * 8);       \
            cp16(sb_ + OFFB_BH + dr_,                                      \
                 Wh + (size_t)(n0 + row_) * Kd + k0_ + part_ * 8);         \
        }                                                                  \
        CP_COMMIT();                                                       \
    } while (0)

    ISSUE_CHUNK(0);

    for (int kt = 0; kt < NC; ++kt) {
        if (kt + 1 < NC) { ISSUE_CHUNK(kt + 1); CP_WAIT(1); }
        else             { CP_WAIT(0); }
        __syncthreads();
        uint32_t sb = smbase + (kt & 1) * STAGE_B;
#pragma unroll
        for (int ks = 0; ks < 32; ks += 16) {
            uint32_t aR[4][4], bH[2][4];
#pragma unroll
            for (int mf = 0; mf < 4; ++mf)
                ldsm4(aR[mf], sb + OFFB_A + aoff + mf * (16 * TSTR * 2) + ks * 2);
#pragma unroll
            for (int p = 0; p < 2; ++p)
                ldsm4(bH[p], sb + OFFB_BH + boff4 + p * (16 * TSTR * 2) + ks * 2);
#pragma unroll
            for (int mf = 0; mf < 4; ++mf)
#pragma unroll
                for (int nf = 0; nf < 4; ++nf)
                    mma16816(acc[mf][nf], aR[mf], &bH[nf >> 1][(nf & 1) << 1]);
        }
        __syncthreads();
    }
#undef ISSUE_CHUNK

#pragma unroll
    for (int mf = 0; mf < 4; ++mf) {
#pragma unroll
        for (int nf = 0; nf < 4; ++nf) {
            int r = m0 + arow + (mf << 4) + g;
            int c = n0 + brow + (nf << 3) + (q << 1);
            if (mode & 2) {
                float t0 = tanhf(acc[mf][nf][0]), t1 = tanhf(acc[mf][nf][1]);
                float t2 = tanhf(acc[mf][nf][2]), t3 = tanhf(acc[mf][nf][3]);
                *(__half2*)(Ch + (size_t)r * N + c) = __floats2half2_rn(t0, t1);
                *(__half2*)(Ch + (size_t)(r + 8) * N + c) = __floats2half2_rn(t2, t3);
            } else {
                float2 v0, v1;
                v0.x = acc[mf][nf][0]; v0.y = acc[mf][nf][1];
                v1.x = acc[mf][nf][2]; v1.y = acc[mf][nf][3];
                *(float2*)(Cf + (size_t)r * N + c) = v0;
                *(float2*)(Cf + (size_t)(r + 8) * N + c) = v1;
            }
        }
    }
}

/* ------------------------------------------------------------------ */
/* weight prep (all layers per launch): transpose + fp16 round         */
/* ------------------------------------------------------------------ */
__global__ void wtrans_all_kernel(const float* __restrict__ W,
                                  __half* __restrict__ wh, int Kd, int N)
{
    int idx = blockIdx.x * 256 + threadIdx.x;
    int per = Kd * N;
    int layer = idx / per, r = idx - layer * per;
    int k = r / N, n = r - k * N;
    float v = W[(size_t)layer * per + (size_t)k * N + n];
    wh[(size_t)layer * per + (size_t)n * Kd + k] = __float2half_rn(v);
}

__global__ void wpackT_all_kernel(const float* __restrict__ Wq,
                                  const float* __restrict__ Wk,
                                  const float* __restrict__ Wv,
                                  __half* __restrict__ wh)
{
    int idx = blockIdx.x * 256 + threadIdx.x;
    int per = CC * QS;
    int layer = idx / per, r = idx - layer * per;
    int k = r / QS, n = r - k * QS;
    const float* src = (n < 256) ? Wq : (n < 512) ? Wk : Wv;
    float v = src[(size_t)layer * CC * CC + (size_t)k * 256 + (n & 255)];
    wh[(size_t)layer * (QS * CC) + (size_t)n * CC + k] = __float2half_rn(v);
}

/* initial x copy + fp16 round, both features into contiguous halves   */
__global__ void split_in_kernel(const float* __restrict__ f0,
                                const float* __restrict__ f1,
                                float* __restrict__ x,
                                __half* __restrict__ xh)
{
    int i = blockIdx.x * 256 + threadIdx.x;
    const float* src = (i < MS * CC) ? f0 : f1 - MS * CC;
    float v = src[i];
    x[i] = v;
    xh[i] = __float2half_rn(v);
}

/* ------------------------------------------------------------------ */
/* Self linear attention — batched over 4 slabs (feature x batch)      */
/* ------------------------------------------------------------------ */
__global__ void __launch_bounds__(256) self_kv_kernel(
    const float* __restrict__ qkv, maskp __restrict__ m0p,
    maskp __restrict__ m1p, float* __restrict__ KVKS)
{
    int blk = blockIdx.x;                /* 512 blocks */
    int ch = blk & 15, h = (blk >> 4) & 7, fb = blk >> 7;
    int tid = threadIdx.x;
    int d = tid >> 3, eq = tid & 7, e0 = eq << 2;
    float a0 = 0.f, a1 = 0.f, a2 = 0.f, a3 = 0.f, accs = 0.f;
    int base = (fb << 12) + (ch << 8);
    maskp mp = ((fb >> 1) ? m1p : m0p) + ((fb & 1) << 12) + (ch << 8);
    const float* kp = qkv + (size_t)base * QS + 256 + h * DD + d;
    const float* vp = qkv + (size_t)base * QS + 512 + h * DD + e0;
#pragma unroll 4
    for (int r = 0; r < 256; ++r) {
        float m = mp[r] ? 1.f : 0.f;
        float kf = m * elu1(kp[(size_t)r * QS]);
        float4 v = *(const float4*)(vp + (size_t)r * QS);
        a0 += kf * v.x; a1 += kf * v.y; a2 += kf * v.z; a3 += kf * v.w;
        accs += kf;
    }
    float* kvp = KVKS + ((size_t)((fb * HH + h) * DD + d) * DD + e0);
    atomicAdd(kvp + 0, a0);
    atomicAdd(kvp + 1, a1);
    atomicAdd(kvp + 2, a2);
    atomicAdd(kvp + 3, a3);
    if (eq == 0) atomicAdd(KVKS + KVSZ + (fb * HH + h) * DD + d, accs);
}

__global__ void __launch_bounds__(256) self_att_kernel(
    const float* __restrict__ qkv, const float* __restrict__ KVKS,
    __half* __restrict__ oh)
{
    __shared__ float sKV[HH][DD][DD];
    __shared__ float sKs[HH][DD];
    __shared__ float sQf[8][CC];
    int tid = threadIdx.x;
    int t0 = blockIdx.x << 3;
    int fb = t0 >> 12;
    for (int i = tid; i < HH * DD * DD; i += 256)
        (&sKV[0][0][0])[i] = KVKS[(size_t)fb * HH * DD * DD + i];
    for (int i = tid; i < HH * DD; i += 256)
        (&sKs[0][0])[i] = KVKS[KVSZ + fb * HH * DD + i];
#pragma unroll
    for (int tt = 0; tt < 8; ++tt)
        sQf[tt][tid] = elu1(qkv[(size_t)(t0 + tt) * QS + tid]);
    __syncthreads();
    int h = tid >> 5, e = tid & 31;
#pragma unroll
    for (int tt = 0; tt < 8; ++tt) {
        float den = sQf[tt][(h << 5) + e] * sKs[h][e];
#pragma unroll
        for (int o = 16; o; o >>= 1) den += __shfl_xor_sync(0xffffffffu, den, o);
        float out = 0.f;
#pragma unroll
        for (int d = 0; d < 32; ++d)
            out += sQf[tt][(h << 5) + d] * sKV[h][d][e];
        oh[(size_t)(t0 + tt) * CC + tid] = __float2half_rn(out / (den + 1e-6f));
    }
}

/* ------------------------------------------------------------------ */
/* bilinear taps + invnorm + cross attention (batched, fp32 gathers)   */
/* ------------------------------------------------------------------ */
__device__ __forceinline__ void taps_of(float kx, float ky, int base,
                                        int* r, float* w)
{
    float px = (((kx - 3.5f) / 507.5f * 2.f - 1.f) + 1.f) * 0.5f * 63.f;
    float py = (((ky - 3.5f) / 507.5f * 2.f - 1.f) + 1.f) * 0.5f * 63.f;
    float x0f = floorf(px), y0f = floorf(py);
    float wx = px - x0f, wy = py - y0f;
    int ix0 = min(max((int)x0f, 0), 63);
    int ix1 = min(max((int)x0f + 1, 0), 63);
    int iy0 = min(max((int)y0f, 0), 63);
    int iy1 = min(max((int)y0f + 1, 0), 63);
    r[0] = base + (iy0 << 6) + ix0;
    r[1] = base + (iy0 << 6) + ix1;
    r[2] = base + (iy1 << 6) + ix0;
    r[3] = base + (iy1 << 6) + ix1;
    w[0] = (1.f - wy) * (1.f - wx);
    w[1] = (1.f - wy) * wx;
    w[2] = wy * (1.f - wx);
    w[3] = wy * wx;
}

__global__ void __launch_bounds__(256) invnorm_kernel(
    const float* __restrict__ x, const float* __restrict__ kp0,
    const float* __restrict__ kp1, float* __restrict__ invn)
{
    int pg = (blockIdx.x << 3) + (threadIdx.x >> 5);
    int lane = threadIdx.x & 31;
    int f = pg >= MD;
    int pl = pg - f * MD;
    const float* kp = f ? kp1 : kp0;
    int b = pl / (LL * KK);
    int r[4]; float w[4];
    taps_of(kp[(size_t)pl * 2], kp[(size_t)pl * 2 + 1],
            f * MS + b * LL, r, w);
    const float* f0 = x + (size_t)r[0] * CC;
    const float* f1 = x + (size_t)r[1] * CC;
    const float* f2 = x + (size_t)r[2] * CC;
    const float* f3 = x + (size_t)r[3] * CC;
    float sq = 0.f;
#pragma unroll
    for (int j = 0; j < 8; ++j) {
        int c = lane + (j << 5);
        float val = w[0]*f0[c] + w[1]*f1[c] + w[2]*f2[c] + w[3]*f3[c];
        sq += val * val;
    }
#pragma unroll
    for (int o = 16; o; o >>= 1) sq += __shfl_xor_sync(0xffffffffu, sq, o);
    if (lane == 0) invn[pg] = 1.f / (sqrtf(sq) + 1e-8f);
}

__global__ void __launch_bounds__(256) cross_att_kernel(
    const float* __restrict__ qkv, const float* __restrict__ kp0,
    const float* __restrict__ kp1, const float* __restrict__ invn,
    maskp __restrict__ mc0, maskp __restrict__ mc1,
    __half* __restrict__ oh)
{
    int t = blockIdx.x;
    int tid = threadIdx.x;
    int h = tid >> 5, lane = tid & 31;
    int f = t >> 13;
    int tok = t & (MS - 1);
    int b = tok >> 12;
    const float* kp = f ? kp0 : kp1;
    const float* inv_base = invn + (size_t)(1 - f) * MD;
    maskp mask = f ? mc0 : mc1;
    int src_base = (1 - f) * MS + b * LL;

    __shared__ float sQf[CC];
    __shared__ int   sTap[KK][4];
    __shared__ float sW[KK][4];
    __shared__ float sInv[KK];
    __shared__ float sM[KK];
    sQf[tid] = elu1(qkv[(size_t)t * QS + tid]);
    if (tid < KK) {
        int p = tok * KK + tid;
        int r[4]; float w[4];
        taps_of(kp[(size_t)p * 2], kp[(size_t)p * 2 + 1], src_base, r, w);
#pragma unroll
        for (int i = 0; i < 4; ++i) { sTap[tid][i] = r[i]; sW[tid][i] = w[i]; }
        sInv[tid] = inv_base[p];
        sM[tid] = mask[p] ? 1.f : 0.f;
    }
    __syncthreads();
    int c = (h << 5) + lane;
    float qf = sQf[c];
    float wgt[KK];
    float den = 0.f;
#pragma unroll
    for (int s = 0; s < KK; ++s) {
        float kraw =
            sW[s][0] * qkv[(size_t)sTap[s][0] * QS + 256 + c] +
            sW[s][1] * qkv[(size_t)sTap[s][1] * QS + 256 + c] +
            sW[s][2] * qkv[(size_t)sTap[s][2] * QS + 256 + c] +
            sW[s][3] * qkv[(size_t)sTap[s][3] * QS + 256 + c];
        float kf = elu1(kraw * sInv[s]) * sM[s];
        float p = qf * kf;
#pragma unroll
        for (int o = 16; o; o >>= 1) p += __shfl_xor_sync(0xffffffffu, p, o);
        wgt[s] = p;
        den += p;
    }
    float inv = 1.f / (den + 1e-6f);
    float out = 0.f;
#pragma unroll
    for (int s = 0; s < KK; ++s) {
        float vraw =
            sW[s][0] * qkv[(size_t)sTap[s][0] * QS + 512 + c] +
            sW[s][1] * qkv[(size_t)sTap[s][1] * QS + 512 + c] +
            sW[s][2] * qkv[(size_t)sTap[s][2] * QS + 512 + c] +
            sW[s][3] * qkv[(size_t)sTap[s][3] * QS + 512 + c];
        out += wgt[s] * (vraw * sInv[s]);
    }
    oh[(size_t)t * CC + tid] = __float2half_rn(out * inv);
}

/* ------------------------------------------------------------------ */
/* LayerNorm (C=256, eps 1e-5)                                         */
/* ------------------------------------------------------------------ */
__device__ __forceinline__ void ln_core(const float* xr, float* v,
                                        float& mean, float& rstd)
{
    int lane = threadIdx.x & 31;
    float s = 0.f;
#pragma unroll
    for (int j = 0; j < 8; ++j) { v[j] = xr[lane + (j << 5)]; s += v[j]; }
#pragma unroll
    for (int o = 16; o; o >>= 1) s += __shfl_xor_sync(0xffffffffu, s, o);
    mean = s * (1.f / 256.f);
    float q = 0.f;
#pragma unroll
    for (int j = 0; j < 8; ++j) { float d = v[j] - mean; q += d * d; }
#pragma unroll
    for (int o = 16; o; o >>= 1) q += __shfl_xor_sync(0xffffffffu, q, o);
    rstd = rsqrtf(q * (1.f / 256.f) + 1e-5f);
}

__global__ void __launch_bounds__(256) ln_split_kernel(
    const float* __restrict__ X, const float* __restrict__ gam,
    const float* __restrict__ bet, __half* __restrict__ oh)
{
    int warp = threadIdx.x >> 5, lane = threadIdx.x & 31;
    int row = (blockIdx.x << 3) + warp;
    float v[8], mean, rstd;
    ln_core(X + (size_t)row * CC, v, mean, rstd);
#pragma unroll
    for (int j = 0; j < 8; ++j) {
        int c = lane + (j << 5);
        float o = (v[j] - mean) * rstd * gam[c] + bet[c];
        oh[(size_t)row * CC + c] = __float2half_rn(o);
    }
}

__global__ void __launch_bounds__(256) ln_add_kernel(
    const float* __restrict__ X, const float* __restrict__ gam,
    const float* __restrict__ bet, float* __restrict__ x,
    __half* __restrict__ xh)
{
    int warp = threadIdx.x >> 5, lane = threadIdx.x & 31;
    int row = (blockIdx.x << 3) + warp;
    float v[8], mean, rstd;
    ln_core(X + (size_t)row * CC, v, mean, rstd);
#pragma unroll
    for (int j = 0; j < 8; ++j) {
        int c = lane + (j << 5);
        float o = (v[j] - mean) * rstd * gam[c] + bet[c];
        float nx = x[(size_t)row * CC + c] + o;
        x[(size_t)row * CC + c] = nx;
        xh[(size_t)row * CC + c] = __float2half_rn(nx);
    }
}

/* ------------------------------------------------------------------ */
/* host orchestration                                                  */
/* ------------------------------------------------------------------ */
struct LayerW {
    const float *g1, *b1, *g2, *b2;
    __half *whP, *whM, *wh1, *wh2;
};
struct Bufs {
    float *t, *kvks;
    __half *atth, *msgh, *uh;
};

static void mlp_tail(float* x, __half* xh, const LayerW& w, const Bufs& s)
{
    hgemm4_kernel<<<dim3(2,128), 256, DSMEM>>>(
        s.atth, (const __half*)0, w.whM, s.t, (__half*)0, CC, CC, 0);
    ln_split_kernel<<<M2/8, 256>>>(s.t, w.g1, w.b1, s.msgh);
    hgemm4_kernel<<<dim3(4,128), 256, DSMEM>>>(
        xh, s.msgh, w.wh1, (float*)0, s.uh, C2, C2, 3);
    hgemm4_kernel<<<dim3(2,128), 256, DSMEM>>>(
        s.uh, (const __half*)0, w.wh2, s.t, (__half*)0, CC, C2, 0);
    ln_add_kernel<<<M2/8, 256>>>(s.t, w.g2, w.b2, x, xh);
}

extern "C" void kernel_launch(void* const* d_in, const int* in_sizes, int n_in,
                              void* d_out, int out_size)
{
    (void)in_sizes; (void)n_in; (void)out_size;
    const float* feat0 = (const float*)d_in[0];
    const float* feat1 = (const float*)d_in[1];
    const float* kp0   = (const float*)d_in[2];
    const float* kp1   = (const float*)d_in[3];
    maskp ms0 = (maskp)d_in[4];
    maskp ms1 = (maskp)d_in[5];
    maskp mc0 = (maskp)d_in[6];
    maskp mc1 = (maskp)d_in[7];
    const float* Wq = (const float*)d_in[8];
    const float* Wk = (const float*)d_in[9];
    const float* Wv = (const float*)d_in[10];
    const float* Wm = (const float*)d_in[11];
    const float* W1 = (const float*)d_in[12];
    const float* W2 = (const float*)d_in[13];
    const float* G1 = (const float*)d_in[14];
    const float* B1 = (const float*)d_in[15];
    const float* G2 = (const float*)d_in[16];
    const float* B2 = (const float*)d_in[17];

    cudaFuncSetAttribute(hgemm4_kernel,
                         cudaFuncAttributeMaxDynamicSharedMemorySize, DSMEM);

    float *px, *pq, *pin;
    __half *pxh;
    __half *whP, *whM, *wh1, *wh2;
    Bufs s;
    cudaGetSymbolAddress((void**)&px, g_x);
    cudaGetSymbolAddress((void**)&pxh, g_xh);
    cudaGetSymbolAddress((void**)&pq, g_qkv);
    cudaGetSymbolAddress((void**)&pin, g_invn);
    cudaGetSymbolAddress((void**)&s.t, g_tb);
    cudaGetSymbolAddress((void**)&s.kvks, g_kvks);
    cudaGetSymbolAddress((void**)&s.atth, g_atth);
    cudaGetSymbolAddress((void**)&s.msgh, g_msgh);
    cudaGetSymbolAddress((void**)&s.uh, g_uh);
    cudaGetSymbolAddress((void**)&whP, g_whP);
    cudaGetSymbolAddress((void**)&whM, g_whM);
    cudaGetSymbolAddress((void**)&wh1, g_wh1);
    cudaGetSymbolAddress((void**)&wh2, g_wh2);

    /* front-loaded weight prep + input round */
    wpackT_all_kernel<<<NL*CC*QS/256, 256>>>(Wq, Wk, Wv, whP);
    wtrans_all_kernel<<<NL*CC*CC/256, 256>>>(Wm, whM, CC, CC);
    wtrans_all_kernel<<<NL*C2*C2/256, 256>>>(W1, wh1, C2, C2);
    wtrans_all_kernel<<<NL*C2*CC/256, 256>>>(W2, wh2, C2, CC);
    split_in_kernel<<<M2*CC/256, 256>>>(feat0, feat1, px, pxh);

    for (int i = 0; i < 4; ++i) {
        LayerW w;
        w.g1 = G1 + (size_t)i * CC;
        w.b1 = B1 + (size_t)i * CC;
        w.g2 = G2 + (size_t)i * CC;
        w.b2 = B2 + (size_t)i * CC;
        w.whP = whP + (size_t)i * QS * CC;
        w.whM = whM + (size_t)i * CC * CC;
        w.wh1 = wh1 + (size_t)i * C2 * C2;
        w.wh2 = wh2 + (size_t)i * C2 * CC;

        hgemm4_kernel<<<dim3(6,128), 256, DSMEM>>>(
            pxh, (const __half*)0, w.whP, pq, (__half*)0, QS, CC, 0);

        if ((i & 1) == 0) {
            cudaMemsetAsync(s.kvks, 0, (size_t)(KVSZ + KSSZ) * sizeof(float), 0);
            self_kv_kernel<<<512, 256>>>(pq, ms0, ms1, s.kvks);
            self_att_kernel<<<M2/8, 256>>>(pq, s.kvks, s.atth);
        } else {
            invnorm_kernel<<<2*MD/8, 256>>>(px, kp0, kp1, pin);
            cross_att_kernel<<<M2, 256>>>(pq, kp0, kp1, pin, mc0, mc1, s.atth);
        }
        mlp_tail(px, pxh, w, s);
    }

    cudaMemcpyAsync(d_out, px, (size_t)M2 * CC * sizeof(float),
                    cudaMemcpyDeviceToDevice, 0);
}

// round 15
// speedup vs baseline: 1.6691x; 1.3857x over previous
#include <cuda_runtime.h>
#include <cuda_fp16.h>
#include <cstdint>
#include <math.h>

#define BB 2
#define LL 4096
#define CC 256
#define C2 512
#define QS 768
#define HH 8
#define DD 32
#define KK 9
#define NL 4
#define MS (BB*LL)          /* rows per feature   */
#define M2 (2*MS)           /* batched rows       */
#define MD (BB*LL*KK)       /* points per feature */
#define KVSZ (4*HH*DD*DD)
#define KSSZ (4*HH*DD)

typedef const unsigned int* maskp;

/* ------------------------------------------------------------------ */
/* device globals — feat0 half then feat1 half, contiguous             */
/* ------------------------------------------------------------------ */
__device__ float  g_x[M2*CC];
__device__ __half g_xh[M2*CC];
__device__ float  g_qkv[M2*QS];
__device__ float  g_invn[2*MD];
__device__ __half g_atth[M2*CC];
__device__ __half g_msgh[M2*CC];
__device__ __half g_uh[M2*C2];
__device__ float  g_tb[M2*CC];
__device__ float  g_kvks[KVSZ + KSSZ];
/* per-layer fp16 transposed weights [N,K] */
__device__ __half g_whP[NL*QS*CC];
__device__ __half g_whM[NL*CC*CC];
__device__ __half g_wh1[NL*C2*C2];
__device__ __half g_wh2[NL*CC*C2];

__device__ __forceinline__ float elu1(float x) { return x > 0.f ? x + 1.f : expf(x); }

__device__ __forceinline__ uint32_t smem_u32(const void* p) {
    uint32_t a;
    asm("{ .reg .u64 t; cvta.to.shared.u64 t, %1; cvt.u32.u64 %0, t; }"
        : "=r"(a) : "l"(p));
    return a;
}
__device__ __forceinline__ void cp16(uint32_t dst, const void* src) {
    asm volatile(
        "{ .reg .u64 g; cvta.to.global.u64 g, %1; "
        "cp.async.cg.shared.global [%0], [g], 16; }"
        :: "r"(dst), "l"(src));
}
#define CP_COMMIT() asm volatile("cp.async.commit_group;")
#define CP_WAIT(n)  asm volatile("cp.async.wait_group %0;" :: "n"(n))

__device__ __forceinline__ void ldsm4(uint32_t* r, uint32_t a) {
    asm volatile("ldmatrix.sync.aligned.m8n8.x4.shared.b16 {%0,%1,%2,%3}, [%4];"
                 : "=r"(r[0]), "=r"(r[1]), "=r"(r[2]), "=r"(r[3]) : "r"(a));
}
__device__ __forceinline__ void mma16816(float* c, const uint32_t* a,
                                         const uint32_t* b) {
    asm volatile(
        "mma.sync.aligned.m16n8k16.row.col.f32.f16.f16.f32 "
        "{%0,%1,%2,%3}, {%4,%5,%6,%7}, {%8,%9}, {%0,%1,%2,%3};"
        : "+f"(c[0]), "+f"(c[1]), "+f"(c[2]), "+f"(c[3])
        : "r"(a[0]), "r"(a[1]), "r"(a[2]), "r"(a[3]), "r"(b[0]), "r"(b[1]));
}

/* ------------------------------------------------------------------ */
/* HMMA GEMM: A fp16, W fp16, cp.async dbl buffer, TSTR=40             */
/* mode bit0: A split across two arrays ([A1|A2], lda=256, Kd=512)     */
/* mode bit1: tanh epilogue + fp16 output (Ch)                         */
/* ------------------------------------------------------------------ */
#define TSTR 40
#define TILE_B (128*TSTR*2)
#define OFFB_A  0
#define OFFB_BH (1*TILE_B)
#define STAGE_B (2*TILE_B)
#define DSMEM   (2*STAGE_B)

__global__ void __launch_bounds__(256, 2)
hgemm4_kernel(const __half* __restrict__ A1, const __half* __restrict__ A2,
              const __half* __restrict__ Wh,
              float* __restrict__ Cf, __half* __restrict__ Ch,
              int N, int Kd, int mode)
{
    extern __shared__ __align__(16) char smh[];
    uint32_t smbase = smem_u32(smh);
    int tid = threadIdx.x, wid = tid >> 5, lane = tid & 31;
    int g = lane >> 2, q = lane & 3;
    int m0 = blockIdx.y << 7, n0 = blockIdx.x << 7;
    int wm = wid >> 2, wn = wid & 3;
    int arow = wm << 6, brow = wn << 5;

    int lr = lane & 7, sel = lane >> 3;
    uint32_t aoff = (uint32_t)(((arow + lr + (sel & 1) * 8) * TSTR
                                + (sel >> 1) * 8) * 2);
    uint32_t boff4 = (uint32_t)(((brow + (sel >> 1) * 8 + lr) * TSTR
                                 + (sel & 1) * 8) * 2);

    float acc[4][4][4];
#pragma unroll
    for (int i = 0; i < 4; ++i)
#pragma unroll
        for (int j = 0; j < 4; ++j)
#pragma unroll
            for (int k = 0; k < 4; ++k) acc[i][j][k] = 0.f;

    const int NC = Kd >> 5;

#define ISSUE_CHUNK(CI) do {                                               \
        int k0_ = (CI) << 5;                                               \
        const __half* a_; int lda_, kl_;                                   \
        if (mode & 1) {                                                    \
            if (k0_ < 256) { a_ = A1; kl_ = k0_; }                         \
            else           { a_ = A2; kl_ = k0_ - 256; }                   \
            lda_ = 256;                                                    \
        } else { a_ = A1; kl_ = k0_; lda_ = Kd; }                          \
        uint32_t sb_ = smbase + ((CI) & 1) * STAGE_B;                      \
        _Pragma("unroll")                                                  \
        for (int i_ = 0; i_ < 2; ++i_) {                                   \
            int s_ = tid + (i_ << 8);                                      \
            int row_ = s_ >> 2, part_ = s_ & 3;                            \
            uint32_t dr_ = (uint32_t)(row_ * (TSTR * 2) + part_ * 16);     \
            cp16(sb_ + OFFB_A + dr_,                                       \
                 a_ + (size_t)(m0 + row_) * lda_ + kl_ + part_ * 8);       \
            cp16(sb_ + OFFB_BH + dr_,                                      \
                 Wh + (size_t)(n0 + row_) * Kd + k0_ + part_ * 8);         \
        }                                                                  \
        CP_COMMIT();                                                       \
    } while (0)

    ISSUE_CHUNK(0);

    for (int kt = 0; kt < NC; ++kt) {
        if (kt + 1 < NC) { ISSUE_CHUNK(kt + 1); CP_WAIT(1); }
        else             { CP_WAIT(0); }
        __syncthreads();
        uint32_t sb = smbase + (kt & 1) * STAGE_B;
#pragma unroll
        for (int ks = 0; ks < 32; ks += 16) {
            uint32_t aR[4][4], bH[2][4];
#pragma unroll
            for (int mf = 0; mf < 4; ++mf)
                ldsm4(aR[mf], sb + OFFB_A + aoff + mf * (16 * TSTR * 2) + ks * 2);
#pragma unroll
            for (int p = 0; p < 2; ++p)
                ldsm4(bH[p], sb + OFFB_BH + boff4 + p * (16 * TSTR * 2) + ks * 2);
#pragma unroll
            for (int mf = 0; mf < 4; ++mf)
#pragma unroll
                for (int nf = 0; nf < 4; ++nf)
                    mma16816(acc[mf][nf], aR[mf], &bH[nf >> 1][(nf & 1) << 1]);
        }
        __syncthreads();
    }
#undef ISSUE_CHUNK

#pragma unroll
    for (int mf = 0; mf < 4; ++mf) {
#pragma unroll
        for (int nf = 0; nf < 4; ++nf) {
            int r = m0 + arow + (mf << 4) + g;
            int c = n0 + brow + (nf << 3) + (q << 1);
            if (mode & 2) {
                float t0 = tanhf(acc[mf][nf][0]), t1 = tanhf(acc[mf][nf][1]);
                float t2 = tanhf(acc[mf][nf][2]), t3 = tanhf(acc[mf][nf][3]);
                *(__half2*)(Ch + (size_t)r * N + c) = __floats2half2_rn(t0, t1);
                *(__half2*)(Ch + (size_t)(r + 8) * N + c) = __floats2half2_rn(t2, t3);
            } else {
                float2 v0, v1;
                v0.x = acc[mf][nf][0]; v0.y = acc[mf][nf][1];
                v1.x = acc[mf][nf][2]; v1.y = acc[mf][nf][3];
                *(float2*)(Cf + (size_t)r * N + c) = v0;
                *(float2*)(Cf + (size_t)(r + 8) * N + c) = v1;
            }
        }
    }
}

/* ------------------------------------------------------------------ */
/* weight prep (all layers per launch): transpose + fp16 round         */
/* ------------------------------------------------------------------ */
__global__ void wtrans_all_kernel(const float* __restrict__ W,
                                  __half* __restrict__ wh, int Kd, int N)
{
    int idx = blockIdx.x * 256 + threadIdx.x;
    int per = Kd * N;
    int layer = idx / per, r = idx - layer * per;
    int k = r / N, n = r - k * N;
    float v = W[(size_t)layer * per + (size_t)k * N + n];
    wh[(size_t)layer * per + (size_t)n * Kd + k] = __float2half_rn(v);
}

__global__ void wpackT_all_kernel(const float* __restrict__ Wq,
                                  const float* __restrict__ Wk,
                                  const float* __restrict__ Wv,
                                  __half* __restrict__ wh)
{
    int idx = blockIdx.x * 256 + threadIdx.x;
    int per = CC * QS;
    int layer = idx / per, r = idx - layer * per;
    int k = r / QS, n = r - k * QS;
    const float* src = (n < 256) ? Wq : (n < 512) ? Wk : Wv;
    float v = src[(size_t)layer * CC * CC + (size_t)k * 256 + (n & 255)];
    wh[(size_t)layer * (QS * CC) + (size_t)n * CC + k] = __float2half_rn(v);
}

/* initial x copy + fp16 round                                          */
__global__ void split_in_kernel(const float* __restrict__ f0,
                                const float* __restrict__ f1,
                                float* __restrict__ x,
                                __half* __restrict__ xh)
{
    int i = blockIdx.x * 256 + threadIdx.x;
    const float* src = (i < MS * CC) ? f0 : f1 - MS * CC;
    float v = src[i];
    x[i] = v;
    xh[i] = __float2half_rn(v);
}

/* ------------------------------------------------------------------ */
/* Self linear attention                                               */
/* ------------------------------------------------------------------ */
__global__ void __launch_bounds__(256) self_kv_kernel(
    const float* __restrict__ qkv, maskp __restrict__ m0p,
    maskp __restrict__ m1p, float* __restrict__ KVKS)
{
    int blk = blockIdx.x;                /* 512 blocks */
    int ch = blk & 15, h = (blk >> 4) & 7, fb = blk >> 7;
    int tid = threadIdx.x;
    int d = tid >> 3, eq = tid & 7, e0 = eq << 2;
    float a0 = 0.f, a1 = 0.f, a2 = 0.f, a3 = 0.f, accs = 0.f;
    int base = (fb << 12) + (ch << 8);
    maskp mp = ((fb >> 1) ? m1p : m0p) + ((fb & 1) << 12) + (ch << 8);
    const float* kp = qkv + (size_t)base * QS + 256 + h * DD + d;
    const float* vp = qkv + (size_t)base * QS + 512 + h * DD + e0;
#pragma unroll 4
    for (int r = 0; r < 256; ++r) {
        float m = mp[r] ? 1.f : 0.f;
        float kf = m * elu1(kp[(size_t)r * QS]);
        float4 v = *(const float4*)(vp + (size_t)r * QS);
        a0 += kf * v.x; a1 += kf * v.y; a2 += kf * v.z; a3 += kf * v.w;
        accs += kf;
    }
    float* kvp = KVKS + ((size_t)((fb * HH + h) * DD + d) * DD + e0);
    atomicAdd(kvp + 0, a0);
    atomicAdd(kvp + 1, a1);
    atomicAdd(kvp + 2, a2);
    atomicAdd(kvp + 3, a3);
    if (eq == 0) atomicAdd(KVKS + KVSZ + (fb * HH + h) * DD + d, accs);
}

__global__ void __launch_bounds__(256) self_att_kernel(
    const float* __restrict__ qkv, const float* __restrict__ KVKS,
    __half* __restrict__ oh)
{
    __shared__ float sKV[HH][DD][DD];
    __shared__ float sKs[HH][DD];
    __shared__ float sQf[8][CC];
    int tid = threadIdx.x;
    int t0 = blockIdx.x << 3;
    int fb = t0 >> 12;
    for (int i = tid; i < HH * DD * DD; i += 256)
        (&sKV[0][0][0])[i] = KVKS[(size_t)fb * HH * DD * DD + i];
    for (int i = tid; i < HH * DD; i += 256)
        (&sKs[0][0])[i] = KVKS[KVSZ + fb * HH * DD + i];
#pragma unroll
    for (int tt = 0; tt < 8; ++tt)
        sQf[tt][tid] = elu1(qkv[(size_t)(t0 + tt) * QS + tid]);
    __syncthreads();
    int h = tid >> 5, e = tid & 31;
#pragma unroll
    for (int tt = 0; tt < 8; ++tt) {
        float den = sQf[tt][(h << 5) + e] * sKs[h][e];
#pragma unroll
        for (int o = 16; o; o >>= 1) den += __shfl_xor_sync(0xffffffffu, den, o);
        float out = 0.f;
#pragma unroll
        for (int d = 0; d < 32; ++d)
            out += sQf[tt][(h << 5) + d] * sKV[h][d][e];
        oh[(size_t)(t0 + tt) * CC + tid] = __float2half_rn(out / (den + 1e-6f));
    }
}

/* ------------------------------------------------------------------ */
/* bilinear taps + invnorm (float4) + cross attention (float4)         */
/* ------------------------------------------------------------------ */
__device__ __forceinline__ void taps_of(float kx, float ky, int base,
                                        int* r, float* w)
{
    float px = (((kx - 3.5f) / 507.5f * 2.f - 1.f) + 1.f) * 0.5f * 63.f;
    float py = (((ky - 3.5f) / 507.5f * 2.f - 1.f) + 1.f) * 0.5f * 63.f;
    float x0f = floorf(px), y0f = floorf(py);
    float wx = px - x0f, wy = py - y0f;
    int ix0 = min(max((int)x0f, 0), 63);
    int ix1 = min(max((int)x0f + 1, 0), 63);
    int iy0 = min(max((int)y0f, 0), 63);
    int iy1 = min(max((int)y0f + 1, 0), 63);
    r[0] = base + (iy0 << 6) + ix0;
    r[1] = base + (iy0 << 6) + ix1;
    r[2] = base + (iy1 << 6) + ix0;
    r[3] = base + (iy1 << 6) + ix1;
    w[0] = (1.f - wy) * (1.f - wx);
    w[1] = (1.f - wy) * wx;
    w[2] = wy * (1.f - wx);
    w[3] = wy * wx;
}

__global__ void __launch_bounds__(256) invnorm_kernel(
    const float* __restrict__ x, const float* __restrict__ kp0,
    const float* __restrict__ kp1, float* __restrict__ invn)
{
    int pg = (blockIdx.x << 3) + (threadIdx.x >> 5);
    int lane = threadIdx.x & 31;
    int f = pg >= MD;
    int pl = pg - f * MD;
    const float* kp = f ? kp1 : kp0;
    int b = pl / (LL * KK);
    int r[4]; float w[4];
    taps_of(kp[(size_t)pl * 2], kp[(size_t)pl * 2 + 1],
            f * MS + b * LL, r, w);
    const float* f0 = x + (size_t)r[0] * CC;
    const float* f1 = x + (size_t)r[1] * CC;
    const float* f2 = x + (size_t)r[2] * CC;
    const float* f3 = x + (size_t)r[3] * CC;
    float sq = 0.f;
#pragma unroll
    for (int jj = 0; jj < 2; ++jj) {
        int c = (jj << 7) + (lane << 2);
        float4 a0 = *(const float4*)(f0 + c);
        float4 a1 = *(const float4*)(f1 + c);
        float4 a2 = *(const float4*)(f2 + c);
        float4 a3 = *(const float4*)(f3 + c);
        float vx = w[0]*a0.x + w[1]*a1.x + w[2]*a2.x + w[3]*a3.x;
        float vy = w[0]*a0.y + w[1]*a1.y + w[2]*a2.y + w[3]*a3.y;
        float vz = w[0]*a0.z + w[1]*a1.z + w[2]*a2.z + w[3]*a3.z;
        float vw = w[0]*a0.w + w[1]*a1.w + w[2]*a2.w + w[3]*a3.w;
        sq += vx*vx + vy*vy + vz*vz + vw*vw;
    }
#pragma unroll
    for (int o = 16; o; o >>= 1) sq += __shfl_xor_sync(0xffffffffu, sq, o);
    if (lane == 0) invn[pg] = 1.f / (sqrtf(sq) + 1e-8f);
}

/* 4 tokens per block, 64 threads (4 channels via float4) per token.   */
/* Per-head dot = 8-thread shfl group (stays inside one warp).          */
__global__ void __launch_bounds__(256) cross_att_kernel(
    const float* __restrict__ qkv, const float* __restrict__ kp0,
    const float* __restrict__ kp1, const float* __restrict__ invn,
    maskp __restrict__ mc0, maskp __restrict__ mc1,
    __half* __restrict__ oh)
{
    int tid = threadIdx.x;
    int tg = tid >> 6, j = tid & 63;
    int t = (blockIdx.x << 2) + tg;
    int f = t >> 13;
    int tok = t & (MS - 1);
    int b = tok >> 12;
    const float* kp = f ? kp0 : kp1;
    const float* inv_base = invn + (size_t)(1 - f) * MD;
    maskp mask = f ? mc0 : mc1;
    int src_base = (1 - f) * MS + b * LL;

    __shared__ int   sTap[4][KK][4];
    __shared__ float sW[4][KK][4];
    __shared__ float sInv[4][KK];
    __shared__ float sM[4][KK];
    if (j < KK) {
        int p = tok * KK + j;
        int r[4]; float w[4];
        taps_of(kp[(size_t)p * 2], kp[(size_t)p * 2 + 1], src_base, r, w);
#pragma unroll
        for (int i = 0; i < 4; ++i) { sTap[tg][j][i] = r[i]; sW[tg][j][i] = w[i]; }
        sInv[tg][j] = inv_base[p];
        sM[tg][j] = mask[p] ? 1.f : 0.f;
    }
    __syncthreads();

    int c4 = j << 2;
    float4 qv = *(const float4*)(qkv + (size_t)t * QS + c4);
    float qf0 = elu1(qv.x), qf1 = elu1(qv.y);
    float qf2 = elu1(qv.z), qf3 = elu1(qv.w);

    float o0 = 0.f, o1 = 0.f, o2 = 0.f, o3 = 0.f, den = 0.f;
#pragma unroll
    for (int s = 0; s < KK; ++s) {
        int r0 = sTap[tg][s][0], r1 = sTap[tg][s][1];
        int r2 = sTap[tg][s][2], r3 = sTap[tg][s][3];
        float w0 = sW[tg][s][0], w1 = sW[tg][s][1];
        float w2 = sW[tg][s][2], w3 = sW[tg][s][3];
        float inv = sInv[tg][s], m = sM[tg][s];

        float4 k0 = *(const float4*)(qkv + (size_t)r0 * QS + 256 + c4);
        float4 k1 = *(const float4*)(qkv + (size_t)r1 * QS + 256 + c4);
        float4 k2 = *(const float4*)(qkv + (size_t)r2 * QS + 256 + c4);
        float4 k3 = *(const float4*)(qkv + (size_t)r3 * QS + 256 + c4);
        float kr0 = w0*k0.x + w1*k1.x + w2*k2.x + w3*k3.x;
        float kr1 = w0*k0.y + w1*k1.y + w2*k2.y + w3*k3.y;
        float kr2 = w0*k0.z + w1*k1.z + w2*k2.z + w3*k3.z;
        float kr3 = w0*k0.w + w1*k1.w + w2*k2.w + w3*k3.w;
        float p = qf0 * (elu1(kr0 * inv) * m) + qf1 * (elu1(kr1 * inv) * m)
                + qf2 * (elu1(kr2 * inv) * m) + qf3 * (elu1(kr3 * inv) * m);
        p += __shfl_xor_sync(0xffffffffu, p, 1);
        p += __shfl_xor_sync(0xffffffffu, p, 2);
        p += __shfl_xor_sync(0xffffffffu, p, 4);
        den += p;

        float4 v0 = *(const float4*)(qkv + (size_t)r0 * QS + 512 + c4);
        float4 v1 = *(const float4*)(qkv + (size_t)r1 * QS + 512 + c4);
        float4 v2 = *(const float4*)(qkv + (size_t)r2 * QS + 512 + c4);
        float4 v3 = *(const float4*)(qkv + (size_t)r3 * QS + 512 + c4);
        float vr0 = w0*v0.x + w1*v1.x + w2*v2.x + w3*v3.x;
        float vr1 = w0*v0.y + w1*v1.y + w2*v2.y + w3*v3.y;
        float vr2 = w0*v0.z + w1*v1.z + w2*v2.z + w3*v3.z;
        float vr3 = w0*v0.w + w1*v1.w + w2*v2.w + w3*v3.w;
        float pi = p * inv;
        o0 += pi * vr0; o1 += pi * vr1; o2 += pi * vr2; o3 += pi * vr3;
    }
    float sc = 1.f / (den + 1e-6f);
    __half2 h01 = __floats2half2_rn(o0 * sc, o1 * sc);
    __half2 h23 = __floats2half2_rn(o2 * sc, o3 * sc);
    *(__half2*)(oh + (size_t)t * CC + c4)     = h01;
    *(__half2*)(oh + (size_t)t * CC + c4 + 2) = h23;
}

/* ------------------------------------------------------------------ */
/* LayerNorm (C=256, eps 1e-5) — float4 loads/stores                   */
/* ------------------------------------------------------------------ */
__device__ __forceinline__ void ln_core4(const float* xr, float4* v,
                                         float& mean, float& rstd)
{
    int lane = threadIdx.x & 31;
    float s = 0.f;
#pragma unroll
    for (int jj = 0; jj < 2; ++jj) {
        v[jj] = *(const float4*)(xr + (lane << 2) + (jj << 7));
        s += v[jj].x + v[jj].y + v[jj].z + v[jj].w;
    }
#pragma unroll
    for (int o = 16; o; o >>= 1) s += __shfl_xor_sync(0xffffffffu, s, o);
    mean = s * (1.f / 256.f);
    float q = 0.f;
#pragma unroll
    for (int jj = 0; jj < 2; ++jj) {
        float dx = v[jj].x - mean, dy = v[jj].y - mean;
        float dz = v[jj].z - mean, dw = v[jj].w - mean;
        q += dx*dx + dy*dy + dz*dz + dw*dw;
    }
#pragma unroll
    for (int o = 16; o; o >>= 1) q += __shfl_xor_sync(0xffffffffu, q, o);
    rstd = rsqrtf(q * (1.f / 256.f) + 1e-5f);
}

__global__ void __launch_bounds__(256) ln_split_kernel(
    const float* __restrict__ X, const float* __restrict__ gam,
    const float* __restrict__ bet, __half* __restrict__ oh)
{
    int warp = threadIdx.x >> 5, lane = threadIdx.x & 31;
    int row = (blockIdx.x << 3) + warp;
    float4 v[2]; float mean, rstd;
    ln_core4(X + (size_t)row * CC, v, mean, rstd);
#pragma unroll
    for (int jj = 0; jj < 2; ++jj) {
        int c = (lane << 2) + (jj << 7);
        float4 gv = *(const float4*)(gam + c);
        float4 bv = *(const float4*)(bet + c);
        float ox = (v[jj].x - mean) * rstd * gv.x + bv.x;
        float oy = (v[jj].y - mean) * rstd * gv.y + bv.y;
        float oz = (v[jj].z - mean) * rstd * gv.z + bv.z;
        float ow = (v[jj].w - mean) * rstd * gv.w + bv.w;
        *(__half2*)(oh + (size_t)row * CC + c)     = __floats2half2_rn(ox, oy);
        *(__half2*)(oh + (size_t)row * CC + c + 2) = __floats2half2_rn(oz, ow);
    }
}

__global__ void __launch_bounds__(256) ln_add_kernel(
    const float* __restrict__ X, const float* __restrict__ gam,
    const float* __restrict__ bet, float* __restrict__ x,
    __half* __restrict__ xh)
{
    int warp = threadIdx.x >> 5, lane = threadIdx.x & 31;
    int row = (blockIdx.x << 3) + warp;
    float4 v[2]; float mean, rstd;
    ln_core4(X + (size_t)row * CC, v, mean, rstd);
#pragma unroll
    for (int jj = 0; jj < 2; ++jj) {
        int c = (lane << 2) + (jj << 7);
        float4 gv = *(const float4*)(gam + c);
        float4 bv = *(const float4*)(bet + c);
        float4 xv = *(const float4*)(x + (size_t)row * CC + c);
        xv.x += (v[jj].x - mean) * rstd * gv.x + bv.x;
        xv.y += (v[jj].y - mean) * rstd * gv.y + bv.y;
        xv.z += (v[jj].z - mean) * rstd * gv.z + bv.z;
        xv.w += (v[jj].w - mean) * rstd * gv.w + bv.w;
        *(float4*)(x + (size_t)row * CC + c) = xv;
        *(__half2*)(xh + (size_t)row * CC + c)     = __floats2half2_rn(xv.x, xv.y);
        *(__half2*)(xh + (size_t)row * CC + c + 2) = __floats2half2_rn(xv.z, xv.w);
    }
}

/* ------------------------------------------------------------------ */
/* host orchestration                                                  */
/* ------------------------------------------------------------------ */
struct LayerW {
    const float *g1, *b1, *g2, *b2;
    __half *whP, *whM, *wh1, *wh2;
};
struct Bufs {
    float *t, *kvks;
    __half *atth, *msgh, *uh;
};

static void mlp_tail(float* x, __half* xh, const LayerW& w, const Bufs& s)
{
    hgemm4_kernel<<<dim3(2,128), 256, DSMEM>>>(
        s.atth, (const __half*)0, w.whM, s.t, (__half*)0, CC, CC, 0);
    ln_split_kernel<<<M2/8, 256>>>(s.t, w.g1, w.b1, s.msgh);
    hgemm4_kernel<<<dim3(4,128), 256, DSMEM>>>(
        xh, s.msgh, w.wh1, (float*)0, s.uh, C2, C2, 3);
    hgemm4_kernel<<<dim3(2,128), 256, DSMEM>>>(
        s.uh, (const __half*)0, w.wh2, s.t, (__half*)0, CC, C2, 0);
    ln_add_kernel<<<M2/8, 256>>>(s.t, w.g2, w.b2, x, xh);
}

extern "C" void kernel_launch(void* const* d_in, const int* in_sizes, int n_in,
                              void* d_out, int out_size)
{
    (void)in_sizes; (void)n_in; (void)out_size;
    const float* feat0 = (const float*)d_in[0];
    const float* feat1 = (const float*)d_in[1];
    const float* kp0   = (const float*)d_in[2];
    const float* kp1   = (const float*)d_in[3];
    maskp ms0 = (maskp)d_in[4];
    maskp ms1 = (maskp)d_in[5];
    maskp mc0 = (maskp)d_in[6];
    maskp mc1 = (maskp)d_in[7];
    const float* Wq = (const float*)d_in[8];
    const float* Wk = (const float*)d_in[9];
    const float* Wv = (const float*)d_in[10];
    const float* Wm = (const float*)d_in[11];
    const float* W1 = (const float*)d_in[12];
    const float* W2 = (const float*)d_in[13];
    const float* G1 = (const float*)d_in[14];
    const float* B1 = (const float*)d_in[15];
    const float* G2 = (const float*)d_in[16];
    const float* B2 = (const float*)d_in[17];

    cudaFuncSetAttribute(hgemm4_kernel,
                         cudaFuncAttributeMaxDynamicSharedMemorySize, DSMEM);

    float *px, *pq, *pin;
    __half *pxh;
    __half *whP, *whM, *wh1, *wh2;
    Bufs s;
    cudaGetSymbolAddress((void**)&px, g_x);
    cudaGetSymbolAddress((void**)&pxh, g_xh);
    cudaGetSymbolAddress((void**)&pq, g_qkv);
    cudaGetSymbolAddress((void**)&pin, g_invn);
    cudaGetSymbolAddress((void**)&s.t, g_tb);
    cudaGetSymbolAddress((void**)&s.kvks, g_kvks);
    cudaGetSymbolAddress((void**)&s.atth, g_atth);
    cudaGetSymbolAddress((void**)&s.msgh, g_msgh);
    cudaGetSymbolAddress((void**)&s.uh, g_uh);
    cudaGetSymbolAddress((void**)&whP, g_whP);
    cudaGetSymbolAddress((void**)&whM, g_whM);
    cudaGetSymbolAddress((void**)&wh1, g_wh1);
    cudaGetSymbolAddress((void**)&wh2, g_wh2);

    /* front-loaded weight prep + input round */
    wpackT_all_kernel<<<NL*CC*QS/256, 256>>>(Wq, Wk, Wv, whP);
    wtrans_all_kernel<<<NL*CC*CC/256, 256>>>(Wm, whM, CC, CC);
    wtrans_all_kernel<<<NL*C2*C2/256, 256>>>(W1, wh1, C2, C2);
    wtrans_all_kernel<<<NL*C2*CC/256, 256>>>(W2, wh2, C2, CC);
    split_in_kernel<<<M2*CC/256, 256>>>(feat0, feat1, px, pxh);

    for (int i = 0; i < 4; ++i) {
        LayerW w;
        w.g1 = G1 + (size_t)i * CC;
        w.b1 = B1 + (size_t)i * CC;
        w.g2 = G2 + (size_t)i * CC;
        w.b2 = B2 + (size_t)i * CC;
        w.whP = whP + (size_t)i * QS * CC;
        w.whM = whM + (size_t)i * CC * CC;
        w.wh1 = wh1 + (size_t)i * C2 * C2;
        w.wh2 = wh2 + (size_t)i * C2 * CC;

        hgemm4_kernel<<<dim3(6,128), 256, DSMEM>>>(
            pxh, (const __half*)0, w.whP, pq, (__half*)0, QS, CC, 0);

        if ((i & 1) == 0) {
            cudaMemsetAsync(s.kvks, 0, (size_t)(KVSZ + KSSZ) * sizeof(float), 0);
            self_kv_kernel<<<512, 256>>>(pq, ms0, ms1, s.kvks);
            self_att_kernel<<<M2/8, 256>>>(pq, s.kvks, s.atth);
        } else {
            invnorm_kernel<<<2*MD/8, 256>>>(px, kp0, kp1, pin);
            cross_att_kernel<<<M2/4, 256>>>(pq, kp0, kp1, pin, mc0, mc1, s.atth);
        }
        mlp_tail(px, pxh, w, s);
    }

    cudaMemcpyAsync(d_out, px, (size_t)M2 * CC * sizeof(float),
                    cudaMemcpyDeviceToDevice, 0);
}

// round 16
// speedup vs baseline: 1.7472x; 1.0468x over previous
#include <cuda_runtime.h>
#include <cuda_fp16.h>
#include <cstdint>
#include <math.h>

#define BB 2
#define LL 4096
#define CC 256
#define C2 512
#define QS 768
#define HH 8
#define DD 32
#define KK 9
#define NL 4
#define MS (BB*LL)          /* rows per feature   */
#define M2 (2*MS)           /* batched rows       */
#define MD (BB*LL*KK)       /* points per feature */
#define KVSZ (4*HH*DD*DD)
#define KSSZ (4*HH*DD)

typedef const unsigned int* maskp;

/* ------------------------------------------------------------------ */
/* device globals — feat0 half then feat1 half, contiguous             */
/* ------------------------------------------------------------------ */
__device__ float  g_x[M2*CC];
__device__ __half g_xh[M2*CC];
__device__ float  g_qkv[M2*QS];
__device__ float  g_invn[2*MD];
__device__ __half g_atth[M2*CC];
__device__ __half g_msgh[M2*CC];
__device__ __half g_uh[M2*C2];
__device__ float  g_tb[M2*CC];
__device__ float  g_kvks[KVSZ + KSSZ];
/* per-layer fp16 transposed weights [N,K] */
__device__ __half g_whP[NL*QS*CC];
__device__ __half g_whM[NL*CC*CC];
__device__ __half g_wh1[NL*C2*C2];
__device__ __half g_wh2[NL*CC*C2];

__device__ __forceinline__ float elu1(float x) { return x > 0.f ? x + 1.f : expf(x); }

__device__ __forceinline__ uint32_t smem_u32(const void* p) {
    uint32_t a;
    asm("{ .reg .u64 t; cvta.to.shared.u64 t, %1; cvt.u32.u64 %0, t; }"
        : "=r"(a) : "l"(p));
    return a;
}
__device__ __forceinline__ void cp16(uint32_t dst, const void* src) {
    asm volatile(
        "{ .reg .u64 g; cvta.to.global.u64 g, %1; "
        "cp.async.cg.shared.global [%0], [g], 16; }"
        :: "r"(dst), "l"(src));
}
#define CP_COMMIT() asm volatile("cp.async.commit_group;")
#define CP_WAIT(n)  asm volatile("cp.async.wait_group %0;" :: "n"(n))

__device__ __forceinline__ void ldsm4(uint32_t* r, uint32_t a) {
    asm volatile("ldmatrix.sync.aligned.m8n8.x4.shared.b16 {%0,%1,%2,%3}, [%4];"
                 : "=r"(r[0]), "=r"(r[1]), "=r"(r[2]), "=r"(r[3]) : "r"(a));
}
__device__ __forceinline__ void mma16816(float* c, const uint32_t* a,
                                         const uint32_t* b) {
    asm volatile(
        "mma.sync.aligned.m16n8k16.row.col.f32.f16.f16.f32 "
        "{%0,%1,%2,%3}, {%4,%5,%6,%7}, {%8,%9}, {%0,%1,%2,%3};"
        : "+f"(c[0]), "+f"(c[1]), "+f"(c[2]), "+f"(c[3])
        : "r"(a[0]), "r"(a[1]), "r"(a[2]), "r"(a[3]), "r"(b[0]), "r"(b[1]));
}

/* ------------------------------------------------------------------ */
/* HMMA GEMM: A fp16, W fp16, cp.async dbl buffer, k-chunk 64          */
/* TSTR=72 (64 halves + 8 pad) — ldsm conflict-free (4i banks)         */
/* mode bit0: A split across two arrays ([A1|A2], lda=256, Kd=512)     */
/* mode bit1: tanh epilogue + fp16 output (Ch)                         */
/* ------------------------------------------------------------------ */
#define TSTR 72
#define TILE_B (128*TSTR*2)           /* 18432 bytes per tile */
#define OFFB_A  0
#define OFFB_BH (1*TILE_B)
#define STAGE_B (2*TILE_B)            /* 36864 */
#define DSMEM   (2*STAGE_B)           /* 73728 */

__global__ void __launch_bounds__(256, 2)
hgemm4_kernel(const __half* __restrict__ A1, const __half* __restrict__ A2,
              const __half* __restrict__ Wh,
              float* __restrict__ Cf, __half* __restrict__ Ch,
              int N, int Kd, int mode)
{
    extern __shared__ __align__(16) char smh[];
    uint32_t smbase = smem_u32(smh);
    int tid = threadIdx.x, wid = tid >> 5, lane = tid & 31;
    int g = lane >> 2, q = lane & 3;
    int m0 = blockIdx.y << 7, n0 = blockIdx.x << 7;
    int wm = wid >> 2, wn = wid & 3;
    int arow = wm << 6, brow = wn << 5;

    int lr = lane & 7, sel = lane >> 3;
    uint32_t aoff = (uint32_t)(((arow + lr + (sel & 1) * 8) * TSTR
                                + (sel >> 1) * 8) * 2);
    uint32_t boff4 = (uint32_t)(((brow + (sel >> 1) * 8 + lr) * TSTR
                                 + (sel & 1) * 8) * 2);

    float acc[4][4][4];
#pragma unroll
    for (int i = 0; i < 4; ++i)
#pragma unroll
        for (int j = 0; j < 4; ++j)
#pragma unroll
            for (int k = 0; k < 4; ++k) acc[i][j][k] = 0.f;

    const int NC = Kd >> 6;

#define ISSUE_CHUNK(CI) do {                                               \
        int k0_ = (CI) << 6;                                               \
        const __half* a_; int lda_, kl_;                                   \
        if (mode & 1) {                                                    \
            if (k0_ < 256) { a_ = A1; kl_ = k0_; }                         \
            else           { a_ = A2; kl_ = k0_ - 256; }                   \
            lda_ = 256;                                                    \
        } else { a_ = A1; kl_ = k0_; lda_ = Kd; }                          \
        uint32_t sb_ = smbase + ((CI) & 1) * STAGE_B;                      \
        _Pragma("unroll")                                                  \
        for (int i_ = 0; i_ < 4; ++i_) {                                   \
            int s_ = tid + (i_ << 8);                                      \
            int row_ = s_ >> 3, part_ = s_ & 7;                            \
            uint32_t dr_ = (uint32_t)(row_ * (TSTR * 2) + part_ * 16);     \
            cp16(sb_ + OFFB_A + dr_,                                       \
                 a_ + (size_t)(m0 + row_) * lda_ + kl_ + part_ * 8);       \
            cp16(sb_ + OFFB_BH + dr_,                                      \
                 Wh + (size_t)(n0 + row_) * Kd + k0_ + part_ * 8);         \
        }                                                                  \
        CP_COMMIT();                                                       \
    } while (0)

    ISSUE_CHUNK(0);

    for (int kt = 0; kt < NC; ++kt) {
        if (kt + 1 < NC) { ISSUE_CHUNK(kt + 1); CP_WAIT(1); }
        else             { CP_WAIT(0); }
        __syncthreads();
        uint32_t sb = smbase + (kt & 1) * STAGE_B;
#pragma unroll
        for (int ks = 0; ks < 64; ks += 16) {
            uint32_t aR[4][4], bH[2][4];
#pragma unroll
            for (int mf = 0; mf < 4; ++mf)
                ldsm4(aR[mf], sb + OFFB_A + aoff + mf * (16 * TSTR * 2) + ks * 2);
#pragma unroll
            for (int p = 0; p < 2; ++p)
                ldsm4(bH[p], sb + OFFB_BH + boff4 + p * (16 * TSTR * 2) + ks * 2);
#pragma unroll
            for (int mf = 0; mf < 4; ++mf)
#pragma unroll
                for (int nf = 0; nf < 4; ++nf)
                    mma16816(acc[mf][nf], aR[mf], &bH[nf >> 1][(nf & 1) << 1]);
        }
        __syncthreads();
    }
#undef ISSUE_CHUNK

#pragma unroll
    for (int mf = 0; mf < 4; ++mf) {
#pragma unroll
        for (int nf = 0; nf < 4; ++nf) {
            int r = m0 + arow + (mf << 4) + g;
            int c = n0 + brow + (nf << 3) + (q << 1);
            if (mode & 2) {
                float t0 = tanhf(acc[mf][nf][0]), t1 = tanhf(acc[mf][nf][1]);
                float t2 = tanhf(acc[mf][nf][2]), t3 = tanhf(acc[mf][nf][3]);
                *(__half2*)(Ch + (size_t)r * N + c) = __floats2half2_rn(t0, t1);
                *(__half2*)(Ch + (size_t)(r + 8) * N + c) = __floats2half2_rn(t2, t3);
            } else {
                float2 v0, v1;
                v0.x = acc[mf][nf][0]; v0.y = acc[mf][nf][1];
                v1.x = acc[mf][nf][2]; v1.y = acc[mf][nf][3];
                *(float2*)(Cf + (size_t)r * N + c) = v0;
                *(float2*)(Cf + (size_t)(r + 8) * N + c) = v1;
            }
        }
    }
}

/* ------------------------------------------------------------------ */
/* weight prep (all layers per launch): transpose + fp16 round         */
/* ------------------------------------------------------------------ */
__global__ void wtrans_all_kernel(const float* __restrict__ W,
                                  __half* __restrict__ wh, int Kd, int N)
{
    int idx = blockIdx.x * 256 + threadIdx.x;
    int per = Kd * N;
    int layer = idx / per, r = idx - layer * per;
    int k = r / N, n = r - k * N;
    float v = W[(size_t)layer * per + (size_t)k * N + n];
    wh[(size_t)layer * per + (size_t)n * Kd + k] = __float2half_rn(v);
}

__global__ void wpackT_all_kernel(const float* __restrict__ Wq,
                                  const float* __restrict__ Wk,
                                  const float* __restrict__ Wv,
                                  __half* __restrict__ wh)
{
    int idx = blockIdx.x * 256 + threadIdx.x;
    int per = CC * QS;
    int layer = idx / per, r = idx - layer * per;
    int k = r / QS, n = r - k * QS;
    const float* src = (n < 256) ? Wq : (n < 512) ? Wk : Wv;
    float v = src[(size_t)layer * CC * CC + (size_t)k * 256 + (n & 255)];
    wh[(size_t)layer * (QS * CC) + (size_t)n * CC + k] = __float2half_rn(v);
}

/* initial x copy + fp16 round                                          */
__global__ void split_in_kernel(const float* __restrict__ f0,
                                const float* __restrict__ f1,
                                float* __restrict__ x,
                                __half* __restrict__ xh)
{
    int i = blockIdx.x * 256 + threadIdx.x;
    const float* src = (i < MS * CC) ? f0 : f1 - MS * CC;
    float v = src[i];
    x[i] = v;
    xh[i] = __float2half_rn(v);
}

/* ------------------------------------------------------------------ */
/* Self linear attention                                               */
/* ------------------------------------------------------------------ */
__global__ void __launch_bounds__(256) self_kv_kernel(
    const float* __restrict__ qkv, maskp __restrict__ m0p,
    maskp __restrict__ m1p, float* __restrict__ KVKS)
{
    int blk = blockIdx.x;                /* 512 blocks */
    int ch = blk & 15, h = (blk >> 4) & 7, fb = blk >> 7;
    int tid = threadIdx.x;
    int d = tid >> 3, eq = tid & 7, e0 = eq << 2;
    float a0 = 0.f, a1 = 0.f, a2 = 0.f, a3 = 0.f, accs = 0.f;
    int base = (fb << 12) + (ch << 8);
    maskp mp = ((fb >> 1) ? m1p : m0p) + ((fb & 1) << 12) + (ch << 8);
    const float* kp = qkv + (size_t)base * QS + 256 + h * DD + d;
    const float* vp = qkv + (size_t)base * QS + 512 + h * DD + e0;
#pragma unroll 4
    for (int r = 0; r < 256; ++r) {
        float m = mp[r] ? 1.f : 0.f;
        float kf = m * elu1(kp[(size_t)r * QS]);
        float4 v = *(const float4*)(vp + (size_t)r * QS);
        a0 += kf * v.x; a1 += kf * v.y; a2 += kf * v.z; a3 += kf * v.w;
        accs += kf;
    }
    float* kvp = KVKS + ((size_t)((fb * HH + h) * DD + d) * DD + e0);
    atomicAdd(kvp + 0, a0);
    atomicAdd(kvp + 1, a1);
    atomicAdd(kvp + 2, a2);
    atomicAdd(kvp + 3, a3);
    if (eq == 0) atomicAdd(KVKS + KVSZ + (fb * HH + h) * DD + d, accs);
}

__global__ void __launch_bounds__(256) self_att_kernel(
    const float* __restrict__ qkv, const float* __restrict__ KVKS,
    __half* __restrict__ oh)
{
    __shared__ float sKV[HH][DD][DD];
    __shared__ float sKs[HH][DD];
    __shared__ float sQf[8][CC];
    int tid = threadIdx.x;
    int t0 = blockIdx.x << 3;
    int fb = t0 >> 12;
    for (int i = tid; i < HH * DD * DD; i += 256)
        (&sKV[0][0][0])[i] = KVKS[(size_t)fb * HH * DD * DD + i];
    for (int i = tid; i < HH * DD; i += 256)
        (&sKs[0][0])[i] = KVKS[KVSZ + fb * HH * DD + i];
#pragma unroll
    for (int tt = 0; tt < 8; ++tt)
        sQf[tt][tid] = elu1(qkv[(size_t)(t0 + tt) * QS + tid]);
    __syncthreads();
    int h = tid >> 5, e = tid & 31;
#pragma unroll
    for (int tt = 0; tt < 8; ++tt) {
        float den = sQf[tt][(h << 5) + e] * sKs[h][e];
#pragma unroll
        for (int o = 16; o; o >>= 1) den += __shfl_xor_sync(0xffffffffu, den, o);
        float out = 0.f;
#pragma unroll
        for (int d = 0; d < 32; ++d)
            out += sQf[tt][(h << 5) + d] * sKV[h][d][e];
        oh[(size_t)(t0 + tt) * CC + tid] = __float2half_rn(out / (den + 1e-6f));
    }
}

/* ------------------------------------------------------------------ */
/* bilinear taps + invnorm (float4) + cross attention (float4)         */
/* ------------------------------------------------------------------ */
__device__ __forceinline__ void taps_of(float kx, float ky, int base,
                                        int* r, float* w)
{
    float px = (((kx - 3.5f) / 507.5f * 2.f - 1.f) + 1.f) * 0.5f * 63.f;
    float py = (((ky - 3.5f) / 507.5f * 2.f - 1.f) + 1.f) * 0.5f * 63.f;
    float x0f = floorf(px), y0f = floorf(py);
    float wx = px - x0f, wy = py - y0f;
    int ix0 = min(max((int)x0f, 0), 63);
    int ix1 = min(max((int)x0f + 1, 0), 63);
    int iy0 = min(max((int)y0f, 0), 63);
    int iy1 = min(max((int)y0f + 1, 0), 63);
    r[0] = base + (iy0 << 6) + ix0;
    r[1] = base + (iy0 << 6) + ix1;
    r[2] = base + (iy1 << 6) + ix0;
    r[3] = base + (iy1 << 6) + ix1;
    w[0] = (1.f - wy) * (1.f - wx);
    w[1] = (1.f - wy) * wx;
    w[2] = wy * (1.f - wx);
    w[3] = wy * wx;
}

__global__ void __launch_bounds__(256) invnorm_kernel(
    const float* __restrict__ x, const float* __restrict__ kp0,
    const float* __restrict__ kp1, float* __restrict__ invn)
{
    int pg = (blockIdx.x << 3) + (threadIdx.x >> 5);
    int lane = threadIdx.x & 31;
    int f = pg >= MD;
    int pl = pg - f * MD;
    const float* kp = f ? kp1 : kp0;
    int b = pl / (LL * KK);
    int r[4]; float w[4];
    taps_of(kp[(size_t)pl * 2], kp[(size_t)pl * 2 + 1],
            f * MS + b * LL, r, w);
    const float* f0 = x + (size_t)r[0] * CC;
    const float* f1 = x + (size_t)r[1] * CC;
    const float* f2 = x + (size_t)r[2] * CC;
    const float* f3 = x + (size_t)r[3] * CC;
    float sq = 0.f;
#pragma unroll
    for (int jj = 0; jj < 2; ++jj) {
        int c = (jj << 7) + (lane << 2);
        float4 a0 = *(const float4*)(f0 + c);
        float4 a1 = *(const float4*)(f1 + c);
        float4 a2 = *(const float4*)(f2 + c);
        float4 a3 = *(const float4*)(f3 + c);
        float vx = w[0]*a0.x + w[1]*a1.x + w[2]*a2.x + w[3]*a3.x;
        float vy = w[0]*a0.y + w[1]*a1.y + w[2]*a2.y + w[3]*a3.y;
        float vz = w[0]*a0.z + w[1]*a1.z + w[2]*a2.z + w[3]*a3.z;
        float vw = w[0]*a0.w + w[1]*a1.w + w[2]*a2.w + w[3]*a3.w;
        sq += vx*vx + vy*vy + vz*vz + vw*vw;
    }
#pragma unroll
    for (int o = 16; o; o >>= 1) sq += __shfl_xor_sync(0xffffffffu, sq, o);
    if (lane == 0) invn[pg] = 1.f / (sqrtf(sq) + 1e-8f);
}

/* 4 tokens per block, 64 threads (4 channels via float4) per token.   */
__global__ void __launch_bounds__(256) cross_att_kernel(
    const float* __restrict__ qkv, const float* __restrict__ kp0,
    const float* __restrict__ kp1, const float* __restrict__ invn,
    maskp __restrict__ mc0, maskp __restrict__ mc1,
    __half* __restrict__ oh)
{
    int tid = threadIdx.x;
    int tg = tid >> 6, j = tid & 63;
    int t = (blockIdx.x << 2) + tg;
    int f = t >> 13;
    int tok = t & (MS - 1);
    int b = tok >> 12;
    const float* kp = f ? kp0 : kp1;
    const float* inv_base = invn + (size_t)(1 - f) * MD;
    maskp mask = f ? mc0 : mc1;
    int src_base = (1 - f) * MS + b * LL;

    __shared__ int   sTap[4][KK][4];
    __shared__ float sW[4][KK][4];
    __shared__ float sInv[4][KK];
    __shared__ float sM[4][KK];
    if (j < KK) {
        int p = tok * KK + j;
        int r[4]; float w[4];
        taps_of(kp[(size_t)p * 2], kp[(size_t)p * 2 + 1], src_base, r, w);
#pragma unroll
        for (int i = 0; i < 4; ++i) { sTap[tg][j][i] = r[i]; sW[tg][j][i] = w[i]; }
        sInv[tg][j] = inv_base[p];
        sM[tg][j] = mask[p] ? 1.f : 0.f;
    }
    __syncthreads();

    int c4 = j << 2;
    float4 qv = *(const float4*)(qkv + (size_t)t * QS + c4);
    float qf0 = elu1(qv.x), qf1 = elu1(qv.y);
    float qf2 = elu1(qv.z), qf3 = elu1(qv.w);

    float o0 = 0.f, o1 = 0.f, o2 = 0.f, o3 = 0.f, den = 0.f;
#pragma unroll
    for (int s = 0; s < KK; ++s) {
        int r0 = sTap[tg][s][0], r1 = sTap[tg][s][1];
        int r2 = sTap[tg][s][2], r3 = sTap[tg][s][3];
        float w0 = sW[tg][s][0], w1 = sW[tg][s][1];
        float w2 = sW[tg][s][2], w3 = sW[tg][s][3];
        float inv = sInv[tg][s], m = sM[tg][s];

        float4 k0 = *(const float4*)(qkv + (size_t)r0 * QS + 256 + c4);
        float4 k1 = *(const float4*)(qkv + (size_t)r1 * QS + 256 + c4);
        float4 k2 = *(const float4*)(qkv + (size_t)r2 * QS + 256 + c4);
        float4 k3 = *(const float4*)(qkv + (size_t)r3 * QS + 256 + c4);
        float kr0 = w0*k0.x + w1*k1.x + w2*k2.x + w3*k3.x;
        float kr1 = w0*k0.y + w1*k1.y + w2*k2.y + w3*k3.y;
        float kr2 = w0*k0.z + w1*k1.z + w2*k2.z + w3*k3.z;
        float kr3 = w0*k0.w + w1*k1.w + w2*k2.w + w3*k3.w;
        float p = qf0 * (elu1(kr0 * inv) * m) + qf1 * (elu1(kr1 * inv) * m)
                + qf2 * (elu1(kr2 * inv) * m) + qf3 * (elu1(kr3 * inv) * m);
        p += __shfl_xor_sync(0xffffffffu, p, 1);
        p += __shfl_xor_sync(0xffffffffu, p, 2);
        p += __shfl_xor_sync(0xffffffffu, p, 4);
        den += p;

        float4 v0 = *(const float4*)(qkv + (size_t)r0 * QS + 512 + c4);
        float4 v1 = *(const float4*)(qkv + (size_t)r1 * QS + 512 + c4);
        float4 v2 = *(const float4*)(qkv + (size_t)r2 * QS + 512 + c4);
        float4 v3 = *(const float4*)(qkv + (size_t)r3 * QS + 512 + c4);
        float vr0 = w0*v0.x + w1*v1.x + w2*v2.x + w3*v3.x;
        float vr1 = w0*v0.y + w1*v1.y + w2*v2.y + w3*v3.y;
        float vr2 = w0*v0.z + w1*v1.z + w2*v2.z + w3*v3.z;
        float vr3 = w0*v0.w + w1*v1.w + w2*v2.w + w3*v3.w;
        float pi = p * inv;
        o0 += pi * vr0; o1 += pi * vr1; o2 += pi * vr2; o3 += pi * vr3;
    }
    float sc = 1.f / (den + 1e-6f);
    __half2 h01 = __floats2half2_rn(o0 * sc, o1 * sc);
    __half2 h23 = __floats2half2_rn(o2 * sc, o3 * sc);
    *(__half2*)(oh + (size_t)t * CC + c4)     = h01;
    *(__half2*)(oh + (size_t)t * CC + c4 + 2) = h23;
}

/* ------------------------------------------------------------------ */
/* LayerNorm (C=256, eps 1e-5) — float4 loads/stores                   */
/* ------------------------------------------------------------------ */
__device__ __forceinline__ void ln_core4(const float* xr, float4* v,
                                         float& mean, float& rstd)
{
    int lane = threadIdx.x & 31;
    float s = 0.f;
#pragma unroll
    for (int jj = 0; jj < 2; ++jj) {
        v[jj] = *(const float4*)(xr + (lane << 2) + (jj << 7));
        s += v[jj].x + v[jj].y + v[jj].z + v[jj].w;
    }
#pragma unroll
    for (int o = 16; o; o >>= 1) s += __shfl_xor_sync(0xffffffffu, s, o);
    mean = s * (1.f / 256.f);
    float q = 0.f;
#pragma unroll
    for (int jj = 0; jj < 2; ++jj) {
        float dx = v[jj].x - mean, dy = v[jj].y - mean;
        float dz = v[jj].z - mean, dw = v[jj].w - mean;
        q += dx*dx + dy*dy + dz*dz + dw*dw;
    }
#pragma unroll
    for (int o = 16; o; o >>= 1) q += __shfl_xor_sync(0xffffffffu, q, o);
    rstd = rsqrtf(q * (1.f / 256.f) + 1e-5f);
}

__global__ void __launch_bounds__(256) ln_split_kernel(
    const float* __restrict__ X, const float* __restrict__ gam,
    const float* __restrict__ bet, __half* __restrict__ oh)
{
    int warp = threadIdx.x >> 5, lane = threadIdx.x & 31;
    int row = (blockIdx.x << 3) + warp;
    float4 v[2]; float mean, rstd;
    ln_core4(X + (size_t)row * CC, v, mean, rstd);
#pragma unroll
    for (int jj = 0; jj < 2; ++jj) {
        int c = (lane << 2) + (jj << 7);
        float4 gv = *(const float4*)(gam + c);
        float4 bv = *(const float4*)(bet + c);
        float ox = (v[jj].x - mean) * rstd * gv.x + bv.x;
        float oy = (v[jj].y - mean) * rstd * gv.y + bv.y;
        float oz = (v[jj].z - mean) * rstd * gv.z + bv.z;
        float ow = (v[jj].w - mean) * rstd * gv.w + bv.w;
        *(__half2*)(oh + (size_t)row * CC + c)     = __floats2half2_rn(ox, oy);
        *(__half2*)(oh + (size_t)row * CC + c + 2) = __floats2half2_rn(oz, ow);
    }
}

__global__ void __launch_bounds__(256) ln_add_kernel(
    const float* __restrict__ X, const float* __restrict__ gam,
    const float* __restrict__ bet, float* __restrict__ x,
    __half* __restrict__ xh)
{
    int warp = threadIdx.x >> 5, lane = threadIdx.x & 31;
    int row = (blockIdx.x << 3) + warp;
    float4 v[2]; float mean, rstd;
    ln_core4(X + (size_t)row * CC, v, mean, rstd);
#pragma unroll
    for (int jj = 0; jj < 2; ++jj) {
        int c = (lane << 2) + (jj << 7);
        float4 gv = *(const float4*)(gam + c);
        float4 bv = *(const float4*)(bet + c);
        float4 xv = *(const float4*)(x + (size_t)row * CC + c);
        xv.x += (v[jj].x - mean) * rstd * gv.x + bv.x;
        xv.y += (v[jj].y - mean) * rstd * gv.y + bv.y;
        xv.z += (v[jj].z - mean) * rstd * gv.z + bv.z;
        xv.w += (v[jj].w - mean) * rstd * gv.w + bv.w;
        *(float4*)(x + (size_t)row * CC + c) = xv;
        *(__half2*)(xh + (size_t)row * CC + c)     = __floats2half2_rn(xv.x, xv.y);
        *(__half2*)(xh + (size_t)row * CC + c + 2) = __floats2half2_rn(xv.z, xv.w);
    }
}

/* ------------------------------------------------------------------ */
/* host orchestration                                                  */
/* ------------------------------------------------------------------ */
struct LayerW {
    const float *g1, *b1, *g2, *b2;
    __half *whP, *whM, *wh1, *wh2;
};
struct Bufs {
    float *t, *kvks;
    __half *atth, *msgh, *uh;
};

static void mlp_tail(float* x, __half* xh, const LayerW& w, const Bufs& s)
{
    hgemm4_kernel<<<dim3(2,128), 256, DSMEM>>>(
        s.atth, (const __half*)0, w.whM, s.t, (__half*)0, CC, CC, 0);
    ln_split_kernel<<<M2/8, 256>>>(s.t, w.g1, w.b1, s.msgh);
    hgemm4_kernel<<<dim3(4,128), 256, DSMEM>>>(
        xh, s.msgh, w.wh1, (float*)0, s.uh, C2, C2, 3);
    hgemm4_kernel<<<dim3(2,128), 256, DSMEM>>>(
        s.uh, (const __half*)0, w.wh2, s.t, (__half*)0, CC, C2, 0);
    ln_add_kernel<<<M2/8, 256>>>(s.t, w.g2, w.b2, x, xh);
}

extern "C" void kernel_launch(void* const* d_in, const int* in_sizes, int n_in,
                              void* d_out, int out_size)
{
    (void)in_sizes; (void)n_in; (void)out_size;
    const float* feat0 = (const float*)d_in[0];
    const float* feat1 = (const float*)d_in[1];
    const float* kp0   = (const float*)d_in[2];
    const float* kp1   = (const float*)d_in[3];
    maskp ms0 = (maskp)d_in[4];
    maskp ms1 = (maskp)d_in[5];
    maskp mc0 = (maskp)d_in[6];
    maskp mc1 = (maskp)d_in[7];
    const float* Wq = (const float*)d_in[8];
    const float* Wk = (const float*)d_in[9];
    const float* Wv = (const float*)d_in[10];
    const float* Wm = (const float*)d_in[11];
    const float* W1 = (const float*)d_in[12];
    const float* W2 = (const float*)d_in[13];
    const float* G1 = (const float*)d_in[14];
    const float* B1 = (const float*)d_in[15];
    const float* G2 = (const float*)d_in[16];
    const float* B2 = (const float*)d_in[17];

    cudaFuncSetAttribute(hgemm4_kernel,
                         cudaFuncAttributeMaxDynamicSharedMemorySize, DSMEM);

    float *px, *pq, *pin;
    __half *pxh;
    __half *whP, *whM, *wh1, *wh2;
    Bufs s;
    cudaGetSymbolAddress((void**)&px, g_x);
    cudaGetSymbolAddress((void**)&pxh, g_xh);
    cudaGetSymbolAddress((void**)&pq, g_qkv);
    cudaGetSymbolAddress((void**)&pin, g_invn);
    cudaGetSymbolAddress((void**)&s.t, g_tb);
    cudaGetSymbolAddress((void**)&s.kvks, g_kvks);
    cudaGetSymbolAddress((void**)&s.atth, g_atth);
    cudaGetSymbolAddress((void**)&s.msgh, g_msgh);
    cudaGetSymbolAddress((void**)&s.uh, g_uh);
    cudaGetSymbolAddress((void**)&whP, g_whP);
    cudaGetSymbolAddress((void**)&whM, g_whM);
    cudaGetSymbolAddress((void**)&wh1, g_wh1);
    cudaGetSymbolAddress((void**)&wh2, g_wh2);

    /* front-loaded weight prep + input round */
    wpackT_all_kernel<<<NL*CC*QS/256, 256>>>(Wq, Wk, Wv, whP);
    wtrans_all_kernel<<<NL*CC*CC/256, 256>>>(Wm, whM, CC, CC);
    wtrans_all_kernel<<<NL*C2*C2/256, 256>>>(W1, wh1, C2, C2);
    wtrans_all_kernel<<<NL*C2*CC/256, 256>>>(W2, wh2, C2, CC);
    split_in_kernel<<<M2*CC/256, 256>>>(feat0, feat1, px, pxh);

    for (int i = 0; i < 4; ++i) {
        LayerW w;
        w.g1 = G1 + (size_t)i * CC;
        w.b1 = B1 + (size_t)i * CC;
        w.g2 = G2 + (size_t)i * CC;
        w.b2 = B2 + (size_t)i * CC;
        w.whP = whP + (size_t)i * QS * CC;
        w.whM = whM + (size_t)i * CC * CC;
        w.wh1 = wh1 + (size_t)i * C2 * C2;
        w.wh2 = wh2 + (size_t)i * C2 * CC;

        hgemm4_kernel<<<dim3(6,128), 256, DSMEM>>>(
            pxh, (const __half*)0, w.whP, pq, (__half*)0, QS, CC, 0);

        if ((i & 1) == 0) {
            cudaMemsetAsync(s.kvks, 0, (size_t)(KVSZ + KSSZ) * sizeof(float), 0);
            self_kv_kernel<<<512, 256>>>(pq, ms0, ms1, s.kvks);
            self_att_kernel<<<M2/8, 256>>>(pq, s.kvks, s.atth);
        } else {
            invnorm_kernel<<<2*MD/8, 256>>>(px, kp0, kp1, pin);
            cross_att_kernel<<<M2/4, 256>>>(pq, kp0, kp1, pin, mc0, mc1, s.atth);
        }
        mlp_tail(px, pxh, w, s);
    }

    cudaMemcpyAsync(d_out, px, (size_t)M2 * CC * sizeof(float),
                    cudaMemcpyDeviceToDevice, 0);
}

// round 17
// speedup vs baseline: 1.7888x; 1.0238x over previous
#include <cuda_runtime.h>
#include <cuda_fp16.h>
#include <cstdint>
#include <math.h>

#define BB 2
#define LL 4096
#define CC 256
#define C2 512
#define QS 768
#define HH 8
#define DD 32
#define KK 9
#define NL 4
#define MS (BB*LL)          /* rows per feature   */
#define M2 (2*MS)           /* batched rows       */
#define MD (BB*LL*KK)       /* points per feature */
#define KVSZ (4*HH*DD*DD)
#define KSSZ (4*HH*DD)

typedef const unsigned int* maskp;

/* ------------------------------------------------------------------ */
/* device globals — feat0 half then feat1 half, contiguous             */
/* ------------------------------------------------------------------ */
__device__ float  g_x[M2*CC];
__device__ __half g_xh[M2*CC];
__device__ float  g_qkv[M2*QS];
__device__ float  g_invn[2*MD];
__device__ __half g_atth[M2*CC];
__device__ __half g_msgh[M2*CC];
__device__ __half g_uh[M2*C2];
__device__ float  g_tb[M2*CC];
__device__ float  g_kvks[KVSZ + KSSZ];
/* per-layer fp16 transposed weights [N,K] */
__device__ __half g_whP[NL*QS*CC];
__device__ __half g_whM[NL*CC*CC];
__device__ __half g_wh1[NL*C2*C2];
__device__ __half g_wh2[NL*CC*C2];

__device__ __forceinline__ float elu1(float x) { return x > 0.f ? x + 1.f : expf(x); }

__device__ __forceinline__ uint32_t smem_u32(const void* p) {
    uint32_t a;
    asm("{ .reg .u64 t; cvta.to.shared.u64 t, %1; cvt.u32.u64 %0, t; }"
        : "=r"(a) : "l"(p));
    return a;
}
__device__ __forceinline__ void cp16(uint32_t dst, const void* src) {
    asm volatile(
        "{ .reg .u64 g; cvta.to.global.u64 g, %1; "
        "cp.async.cg.shared.global [%0], [g], 16; }"
        :: "r"(dst), "l"(src));
}
#define CP_COMMIT() asm volatile("cp.async.commit_group;")
#define CP_WAIT(n)  asm volatile("cp.async.wait_group %0;" :: "n"(n))

__device__ __forceinline__ void ldsm4(uint32_t* r, uint32_t a) {
    asm volatile("ldmatrix.sync.aligned.m8n8.x4.shared.b16 {%0,%1,%2,%3}, [%4];"
                 : "=r"(r[0]), "=r"(r[1]), "=r"(r[2]), "=r"(r[3]) : "r"(a));
}
__device__ __forceinline__ void mma16816(float* c, const uint32_t* a,
                                         const uint32_t* b) {
    asm volatile(
        "mma.sync.aligned.m16n8k16.row.col.f32.f16.f16.f32 "
        "{%0,%1,%2,%3}, {%4,%5,%6,%7}, {%8,%9}, {%0,%1,%2,%3};"
        : "+f"(c[0]), "+f"(c[1]), "+f"(c[2]), "+f"(c[3])
        : "r"(a[0]), "r"(a[1]), "r"(a[2]), "r"(a[3]), "r"(b[0]), "r"(b[1]));
}

/* ------------------------------------------------------------------ */
/* HMMA GEMM: A fp16, W fp16, cp.async 3-stage ring, k-chunk 64        */
/* ONE __syncthreads per chunk; issue(kt+2) overlaps compute(kt)       */
/* TSTR=72 (64 halves + 8 pad) — ldsm conflict-free                    */
/* mode bit0: A split across two arrays ([A1|A2], lda=256, Kd=512)     */
/* mode bit1: tanh epilogue + fp16 output (Ch)                         */
/* ------------------------------------------------------------------ */
#define TSTR 72
#define TILE_B (128*TSTR*2)           /* 18432 bytes per tile */
#define OFFB_A  0
#define OFFB_BH (1*TILE_B)
#define STAGE_B (2*TILE_B)            /* 36864 */
#define DSMEM   (3*STAGE_B)           /* 110592 */

__global__ void __launch_bounds__(256, 2)
hgemm4_kernel(const __half* __restrict__ A1, const __half* __restrict__ A2,
              const __half* __restrict__ Wh,
              float* __restrict__ Cf, __half* __restrict__ Ch,
              int N, int Kd, int mode)
{
    extern __shared__ __align__(16) char smh[];
    uint32_t smbase = smem_u32(smh);
    int tid = threadIdx.x, wid = tid >> 5, lane = tid & 31;
    int g = lane >> 2, q = lane & 3;
    int m0 = blockIdx.y << 7, n0 = blockIdx.x << 7;
    int wm = wid >> 2, wn = wid & 3;
    int arow = wm << 6, brow = wn << 5;

    int lr = lane & 7, sel = lane >> 3;
    uint32_t aoff = (uint32_t)(((arow + lr + (sel & 1) * 8) * TSTR
                                + (sel >> 1) * 8) * 2);
    uint32_t boff4 = (uint32_t)(((brow + (sel >> 1) * 8 + lr) * TSTR
                                 + (sel & 1) * 8) * 2);

    float acc[4][4][4];
#pragma unroll
    for (int i = 0; i < 4; ++i)
#pragma unroll
        for (int j = 0; j < 4; ++j)
#pragma unroll
            for (int k = 0; k < 4; ++k) acc[i][j][k] = 0.f;

    const int NC = Kd >> 6;

#define ISSUE_CHUNK(CI, ST) do {                                           \
        int k0_ = (CI) << 6;                                               \
        const __half* a_; int lda_, kl_;                                   \
        if (mode & 1) {                                                    \
            if (k0_ < 256) { a_ = A1; kl_ = k0_; }                         \
            else           { a_ = A2; kl_ = k0_ - 256; }                   \
            lda_ = 256;                                                    \
        } else { a_ = A1; kl_ = k0_; lda_ = Kd; }                          \
        uint32_t sb_ = smbase + (uint32_t)(ST) * STAGE_B;                  \
        _Pragma("unroll")                                                  \
        for (int i_ = 0; i_ < 4; ++i_) {                                   \
            int s_ = tid + (i_ << 8);                                      \
            int row_ = s_ >> 3, part_ = s_ & 7;                            \
            uint32_t dr_ = (uint32_t)(row_ * (TSTR * 2) + part_ * 16);     \
            cp16(sb_ + OFFB_A + dr_,                                       \
                 a_ + (size_t)(m0 + row_) * lda_ + kl_ + part_ * 8);       \
            cp16(sb_ + OFFB_BH + dr_,                                      \
                 Wh + (size_t)(n0 + row_) * Kd + k0_ + part_ * 8);         \
        }                                                                  \
        CP_COMMIT();                                                       \
    } while (0)

    ISSUE_CHUNK(0, 0);
    if (NC > 1) ISSUE_CHUNK(1, 1);
    else        CP_COMMIT();           /* keep group count aligned */

    int st = 0;
    for (int kt = 0; kt < NC; ++kt) {
        CP_WAIT(1);                     /* chunk kt landed */
        __syncthreads();                /* visible to all; prior compute done */
        if (kt + 2 < NC) {
            int st2 = st + 2; if (st2 >= 3) st2 -= 3;
            ISSUE_CHUNK(kt + 2, st2);
        } else {
            CP_COMMIT();                /* keep one group per iteration */
        }
        uint32_t sb = smbase + (uint32_t)st * STAGE_B;
#pragma unroll
        for (int ks = 0; ks < 64; ks += 16) {
            uint32_t aR[4][4], bH[2][4];
#pragma unroll
            for (int mf = 0; mf < 4; ++mf)
                ldsm4(aR[mf], sb + OFFB_A + aoff + mf * (16 * TSTR * 2) + ks * 2);
#pragma unroll
            for (int p = 0; p < 2; ++p)
                ldsm4(bH[p], sb + OFFB_BH + boff4 + p * (16 * TSTR * 2) + ks * 2);
#pragma unroll
            for (int mf = 0; mf < 4; ++mf)
#pragma unroll
                for (int nf = 0; nf < 4; ++nf)
                    mma16816(acc[mf][nf], aR[mf], &bH[nf >> 1][(nf & 1) << 1]);
        }
        if (++st == 3) st = 0;
    }
#undef ISSUE_CHUNK

#pragma unroll
    for (int mf = 0; mf < 4; ++mf) {
#pragma unroll
        for (int nf = 0; nf < 4; ++nf) {
            int r = m0 + arow + (mf << 4) + g;
            int c = n0 + brow + (nf << 3) + (q << 1);
            if (mode & 2) {
                float t0 = tanhf(acc[mf][nf][0]), t1 = tanhf(acc[mf][nf][1]);
                float t2 = tanhf(acc[mf][nf][2]), t3 = tanhf(acc[mf][nf][3]);
                *(__half2*)(Ch + (size_t)r * N + c) = __floats2half2_rn(t0, t1);
                *(__half2*)(Ch + (size_t)(r + 8) * N + c) = __floats2half2_rn(t2, t3);
            } else {
                float2 v0, v1;
                v0.x = acc[mf][nf][0]; v0.y = acc[mf][nf][1];
                v1.x = acc[mf][nf][2]; v1.y = acc[mf][nf][3];
                *(float2*)(Cf + (size_t)r * N + c) = v0;
                *(float2*)(Cf + (size_t)(r + 8) * N + c) = v1;
            }
        }
    }
}

/* ------------------------------------------------------------------ */
/* weight prep (all layers per launch): transpose + fp16 round         */
/* ------------------------------------------------------------------ */
__global__ void wtrans_all_kernel(const float* __restrict__ W,
                                  __half* __restrict__ wh, int Kd, int N)
{
    int idx = blockIdx.x * 256 + threadIdx.x;
    int per = Kd * N;
    int layer = idx / per, r = idx - layer * per;
    int k = r / N, n = r - k * N;
    float v = W[(size_t)layer * per + (size_t)k * N + n];
    wh[(size_t)layer * per + (size_t)n * Kd + k] = __float2half_rn(v);
}

__global__ void wpackT_all_kernel(const float* __restrict__ Wq,
                                  const float* __restrict__ Wk,
                                  const float* __restrict__ Wv,
                                  __half* __restrict__ wh)
{
    int idx = blockIdx.x * 256 + threadIdx.x;
    int per = CC * QS;
    int layer = idx / per, r = idx - layer * per;
    int k = r / QS, n = r - k * QS;
    const float* src = (n < 256) ? Wq : (n < 512) ? Wk : Wv;
    float v = src[(size_t)layer * CC * CC + (size_t)k * 256 + (n & 255)];
    wh[(size_t)layer * (QS * CC) + (size_t)n * CC + k] = __float2half_rn(v);
}

/* initial x copy + fp16 round                                          */
__global__ void split_in_kernel(const float* __restrict__ f0,
                                const float* __restrict__ f1,
                                float* __restrict__ x,
                                __half* __restrict__ xh)
{
    int i = blockIdx.x * 256 + threadIdx.x;
    const float* src = (i < MS * CC) ? f0 : f1 - MS * CC;
    float v = src[i];
    x[i] = v;
    xh[i] = __float2half_rn(v);
}

/* ------------------------------------------------------------------ */
/* Self linear attention                                               */
/* ------------------------------------------------------------------ */
__global__ void __launch_bounds__(256) self_kv_kernel(
    const float* __restrict__ qkv, maskp __restrict__ m0p,
    maskp __restrict__ m1p, float* __restrict__ KVKS)
{
    int blk = blockIdx.x;                /* 512 blocks */
    int ch = blk & 15, h = (blk >> 4) & 7, fb = blk >> 7;
    int tid = threadIdx.x;
    int d = tid >> 3, eq = tid & 7, e0 = eq << 2;
    float a0 = 0.f, a1 = 0.f, a2 = 0.f, a3 = 0.f, accs = 0.f;
    int base = (fb << 12) + (ch << 8);
    maskp mp = ((fb >> 1) ? m1p : m0p) + ((fb & 1) << 12) + (ch << 8);
    const float* kp = qkv + (size_t)base * QS + 256 + h * DD + d;
    const float* vp = qkv + (size_t)base * QS + 512 + h * DD + e0;
#pragma unroll 4
    for (int r = 0; r < 256; ++r) {
        float m = mp[r] ? 1.f : 0.f;
        float kf = m * elu1(kp[(size_t)r * QS]);
        float4 v = *(const float4*)(vp + (size_t)r * QS);
        a0 += kf * v.x; a1 += kf * v.y; a2 += kf * v.z; a3 += kf * v.w;
        accs += kf;
    }
    float* kvp = KVKS + ((size_t)((fb * HH + h) * DD + d) * DD + e0);
    atomicAdd(kvp + 0, a0);
    atomicAdd(kvp + 1, a1);
    atomicAdd(kvp + 2, a2);
    atomicAdd(kvp + 3, a3);
    if (eq == 0) atomicAdd(KVKS + KVSZ + (fb * HH + h) * DD + d, accs);
}

__global__ void __launch_bounds__(256) self_att_kernel(
    const float* __restrict__ qkv, const float* __restrict__ KVKS,
    __half* __restrict__ oh)
{
    __shared__ float sKV[HH][DD][DD];
    __shared__ float sKs[HH][DD];
    __shared__ float sQf[8][CC];
    int tid = threadIdx.x;
    int t0 = blockIdx.x << 3;
    int fb = t0 >> 12;
    for (int i = tid; i < HH * DD * DD; i += 256)
        (&sKV[0][0][0])[i] = KVKS[(size_t)fb * HH * DD * DD + i];
    for (int i = tid; i < HH * DD; i += 256)
        (&sKs[0][0])[i] = KVKS[KVSZ + fb * HH * DD + i];
#pragma unroll
    for (int tt = 0; tt < 8; ++tt)
        sQf[tt][tid] = elu1(qkv[(size_t)(t0 + tt) * QS + tid]);
    __syncthreads();
    int h = tid >> 5, e = tid & 31;
#pragma unroll
    for (int tt = 0; tt < 8; ++tt) {
        float den = sQf[tt][(h << 5) + e] * sKs[h][e];
#pragma unroll
        for (int o = 16; o; o >>= 1) den += __shfl_xor_sync(0xffffffffu, den, o);
        float out = 0.f;
#pragma unroll
        for (int d = 0; d < 32; ++d)
            out += sQf[tt][(h << 5) + d] * sKV[h][d][e];
        oh[(size_t)(t0 + tt) * CC + tid] = __float2half_rn(out / (den + 1e-6f));
    }
}

/* ------------------------------------------------------------------ */
/* bilinear taps + invnorm (float4) + cross attention (float4)         */
/* ------------------------------------------------------------------ */
__device__ __forceinline__ void taps_of(float kx, float ky, int base,
                                        int* r, float* w)
{
    float px = (((kx - 3.5f) / 507.5f * 2.f - 1.f) + 1.f) * 0.5f * 63.f;
    float py = (((ky - 3.5f) / 507.5f * 2.f - 1.f) + 1.f) * 0.5f * 63.f;
    float x0f = floorf(px), y0f = floorf(py);
    float wx = px - x0f, wy = py - y0f;
    int ix0 = min(max((int)x0f, 0), 63);
    int ix1 = min(max((int)x0f + 1, 0), 63);
    int iy0 = min(max((int)y0f, 0), 63);
    int iy1 = min(max((int)y0f + 1, 0), 63);
    r[0] = base + (iy0 << 6) + ix0;
    r[1] = base + (iy0 << 6) + ix1;
    r[2] = base + (iy1 << 6) + ix0;
    r[3] = base + (iy1 << 6) + ix1;
    w[0] = (1.f - wy) * (1.f - wx);
    w[1] = (1.f - wy) * wx;
    w[2] = wy * (1.f - wx);
    w[3] = wy * wx;
}

__global__ void __launch_bounds__(256) invnorm_kernel(
    const float* __restrict__ x, const float* __restrict__ kp0,
    const float* __restrict__ kp1, float* __restrict__ invn)
{
    int pg = (blockIdx.x << 3) + (threadIdx.x >> 5);
    int lane = threadIdx.x & 31;
    int f = pg >= MD;
    int pl = pg - f * MD;
    const float* kp = f ? kp1 : kp0;
    int b = pl / (LL * KK);
    int r[4]; float w[4];
    taps_of(kp[(size_t)pl * 2], kp[(size_t)pl * 2 + 1],
            f * MS + b * LL, r, w);
    const float* f0 = x + (size_t)r[0] * CC;
    const float* f1 = x + (size_t)r[1] * CC;
    const float* f2 = x + (size_t)r[2] * CC;
    const float* f3 = x + (size_t)r[3] * CC;
    float sq = 0.f;
#pragma unroll
    for (int jj = 0; jj < 2; ++jj) {
        int c = (jj << 7) + (lane << 2);
        float4 a0 = *(const float4*)(f0 + c);
        float4 a1 = *(const float4*)(f1 + c);
        float4 a2 = *(const float4*)(f2 + c);
        float4 a3 = *(const float4*)(f3 + c);
        float vx = w[0]*a0.x + w[1]*a1.x + w[2]*a2.x + w[3]*a3.x;
        float vy = w[0]*a0.y + w[1]*a1.y + w[2]*a2.y + w[3]*a3.y;
        float vz = w[0]*a0.z + w[1]*a1.z + w[2]*a2.z + w[3]*a3.z;
        float vw = w[0]*a0.w + w[1]*a1.w + w[2]*a2.w + w[3]*a3.w;
        sq += vx*vx + vy*vy + vz*vz + vw*vw;
    }
#pragma unroll
    for (int o = 16; o; o >>= 1) sq += __shfl_xor_sync(0xffffffffu, sq, o);
    if (lane == 0) invn[pg] = 1.f / (sqrtf(sq) + 1e-8f);
}

/* 4 tokens per block, 64 threads (4 channels via float4) per token.   */
__global__ void __launch_bounds__(256) cross_att_kernel(
    const float* __restrict__ qkv, const float* __restrict__ kp0,
    const float* __restrict__ kp1, const float* __restrict__ invn,
    maskp __restrict__ mc0, maskp __restrict__ mc1,
    __half* __restrict__ oh)
{
    int tid = threadIdx.x;
    int tg = tid >> 6, j = tid & 63;
    int t = (blockIdx.x << 2) + tg;
    int f = t >> 13;
    int tok = t & (MS - 1);
    int b = tok >> 12;
    const float* kp = f ? kp0 : kp1;
    const float* inv_base = invn + (size_t)(1 - f) * MD;
    maskp mask = f ? mc0 : mc1;
    int src_base = (1 - f) * MS + b * LL;

    __shared__ int   sTap[4][KK][4];
    __shared__ float sW[4][KK][4];
    __shared__ float sInv[4][KK];
    __shared__ float sM[4][KK];
    if (j < KK) {
        int p = tok * KK + j;
        int r[4]; float w[4];
        taps_of(kp[(size_t)p * 2], kp[(size_t)p * 2 + 1], src_base, r, w);
#pragma unroll
        for (int i = 0; i < 4; ++i) { sTap[tg][j][i] = r[i]; sW[tg][j][i] = w[i]; }
        sInv[tg][j] = inv_base[p];
        sM[tg][j] = mask[p] ? 1.f : 0.f;
    }
    __syncthreads();

    int c4 = j << 2;
    float4 qv = *(const float4*)(qkv + (size_t)t * QS + c4);
    float qf0 = elu1(qv.x), qf1 = elu1(qv.y);
    float qf2 = elu1(qv.z), qf3 = elu1(qv.w);

    float o0 = 0.f, o1 = 0.f, o2 = 0.f, o3 = 0.f, den = 0.f;
#pragma unroll
    for (int s = 0; s < KK; ++s) {
        int r0 = sTap[tg][s][0], r1 = sTap[tg][s][1];
        int r2 = sTap[tg][s][2], r3 = sTap[tg][s][3];
        float w0 = sW[tg][s][0], w1 = sW[tg][s][1];
        float w2 = sW[tg][s][2], w3 = sW[tg][s][3];
        float inv = sInv[tg][s], m = sM[tg][s];

        float4 k0 = *(const float4*)(qkv + (size_t)r0 * QS + 256 + c4);
        float4 k1 = *(const float4*)(qkv + (size_t)r1 * QS + 256 + c4);
        float4 k2 = *(const float4*)(qkv + (size_t)r2 * QS + 256 + c4);
        float4 k3 = *(const float4*)(qkv + (size_t)r3 * QS + 256 + c4);
        float kr0 = w0*k0.x + w1*k1.x + w2*k2.x + w3*k3.x;
        float kr1 = w0*k0.y + w1*k1.y + w2*k2.y + w3*k3.y;
        float kr2 = w0*k0.z + w1*k1.z + w2*k2.z + w3*k3.z;
        float kr3 = w0*k0.w + w1*k1.w + w2*k2.w + w3*k3.w;
        float p = qf0 * (elu1(kr0 * inv) * m) + qf1 * (elu1(kr1 * inv) * m)
                + qf2 * (elu1(kr2 * inv) * m) + qf3 * (elu1(kr3 * inv) * m);
        p += __shfl_xor_sync(0xffffffffu, p, 1);
        p += __shfl_xor_sync(0xffffffffu, p, 2);
        p += __shfl_xor_sync(0xffffffffu, p, 4);
        den += p;

        float4 v0 = *(const float4*)(qkv + (size_t)r0 * QS + 512 + c4);
        float4 v1 = *(const float4*)(qkv + (size_t)r1 * QS + 512 + c4);
        float4 v2 = *(const float4*)(qkv + (size_t)r2 * QS + 512 + c4);
        float4 v3 = *(const float4*)(qkv + (size_t)r3 * QS + 512 + c4);
        float vr0 = w0*v0.x + w1*v1.x + w2*v2.x + w3*v3.x;
        float vr1 = w0*v0.y + w1*v1.y + w2*v2.y + w3*v3.y;
        float vr2 = w0*v0.z + w1*v1.z + w2*v2.z + w3*v3.z;
        float vr3 = w0*v0.w + w1*v1.w + w2*v2.w + w3*v3.w;
        float pi = p * inv;
        o0 += pi * vr0; o1 += pi * vr1; o2 += pi * vr2; o3 += pi * vr3;
    }
    float sc = 1.f / (den + 1e-6f);
    __half2 h01 = __floats2half2_rn(o0 * sc, o1 * sc);
    __half2 h23 = __floats2half2_rn(o2 * sc, o3 * sc);
    *(__half2*)(oh + (size_t)t * CC + c4)     = h01;
    *(__half2*)(oh + (size_t)t * CC + c4 + 2) = h23;
}

/* ------------------------------------------------------------------ */
/* LayerNorm (C=256, eps 1e-5) — float4 loads/stores                   */
/* ------------------------------------------------------------------ */
__device__ __forceinline__ void ln_core4(const float* xr, float4* v,
                                         float& mean, float& rstd)
{
    int lane = threadIdx.x & 31;
    float s = 0.f;
#pragma unroll
    for (int jj = 0; jj < 2; ++jj) {
        v[jj] = *(const float4*)(xr + (lane << 2) + (jj << 7));
        s += v[jj].x + v[jj].y + v[jj].z + v[jj].w;
    }
#pragma unroll
    for (int o = 16; o; o >>= 1) s += __shfl_xor_sync(0xffffffffu, s, o);
    mean = s * (1.f / 256.f);
    float q = 0.f;
#pragma unroll
    for (int jj = 0; jj < 2; ++jj) {
        float dx = v[jj].x - mean, dy = v[jj].y - mean;
        float dz = v[jj].z - mean, dw = v[jj].w - mean;
        q += dx*dx + dy*dy + dz*dz + dw*dw;
    }
#pragma unroll
    for (int o = 16; o; o >>= 1) q += __shfl_xor_sync(0xffffffffu, q, o);
    rstd = rsqrtf(q * (1.f / 256.f) + 1e-5f);
}

__global__ void __launch_bounds__(256) ln_split_kernel(
    const float* __restrict__ X, const float* __restrict__ gam,
    const float* __restrict__ bet, __half* __restrict__ oh)
{
    int warp = threadIdx.x >> 5, lane = threadIdx.x & 31;
    int row = (blockIdx.x << 3) + warp;
    float4 v[2]; float mean, rstd;
    ln_core4(X + (size_t)row * CC, v, mean, rstd);
#pragma unroll
    for (int jj = 0; jj < 2; ++jj) {
        int c = (lane << 2) + (jj << 7);
        float4 gv = *(const float4*)(gam + c);
        float4 bv = *(const float4*)(bet + c);
        float ox = (v[jj].x - mean) * rstd * gv.x + bv.x;
        float oy = (v[jj].y - mean) * rstd * gv.y + bv.y;
        float oz = (v[jj].z - mean) * rstd * gv.z + bv.z;
        float ow = (v[jj].w - mean) * rstd * gv.w + bv.w;
        *(__half2*)(oh + (size_t)row * CC + c)     = __floats2half2_rn(ox, oy);
        *(__half2*)(oh + (size_t)row * CC + c + 2) = __floats2half2_rn(oz, ow);
    }
}

__global__ void __launch_bounds__(256) ln_add_kernel(
    const float* __restrict__ X, const float* __restrict__ gam,
    const float* __restrict__ bet, float* __restrict__ x,
    __half* __restrict__ xh)
{
    int warp = threadIdx.x >> 5, lane = threadIdx.x & 31;
    int row = (blockIdx.x << 3) + warp;
    float4 v[2]; float mean, rstd;
    ln_core4(X + (size_t)row * CC, v, mean, rstd);
#pragma unroll
    for (int jj = 0; jj < 2; ++jj) {
        int c = (lane << 2) + (jj << 7);
        float4 gv = *(const float4*)(gam + c);
        float4 bv = *(const float4*)(bet + c);
        float4 xv = *(const float4*)(x + (size_t)row * CC + c);
        xv.x += (v[jj].x - mean) * rstd * gv.x + bv.x;
        xv.y += (v[jj].y - mean) * rstd * gv.y + bv.y;
        xv.z += (v[jj].z - mean) * rstd * gv.z + bv.z;
        xv.w += (v[jj].w - mean) * rstd * gv.w + bv.w;
        *(float4*)(x + (size_t)row * CC + c) = xv;
        *(__half2*)(xh + (size_t)row * CC + c)     = __floats2half2_rn(xv.x, xv.y);
        *(__half2*)(xh + (size_t)row * CC + c + 2) = __floats2half2_rn(xv.z, xv.w);
    }
}

/* ------------------------------------------------------------------ */
/* host orchestration                                                  */
/* ------------------------------------------------------------------ */
struct LayerW {
    const float *g1, *b1, *g2, *b2;
    __half *whP, *whM, *wh1, *wh2;
};
struct Bufs {
    float *t, *kvks;
    __half *atth, *msgh, *uh;
};

static void mlp_tail(float* x, __half* xh, const LayerW& w, const Bufs& s)
{
    hgemm4_kernel<<<dim3(2,128), 256, DSMEM>>>(
        s.atth, (const __half*)0, w.whM, s.t, (__half*)0, CC, CC, 0);
    ln_split_kernel<<<M2/8, 256>>>(s.t, w.g1, w.b1, s.msgh);
    hgemm4_kernel<<<dim3(4,128), 256, DSMEM>>>(
        xh, s.msgh, w.wh1, (float*)0, s.uh, C2, C2, 3);
    hgemm4_kernel<<<dim3(2,128), 256, DSMEM>>>(
        s.uh, (const __half*)0, w.wh2, s.t, (__half*)0, CC, C2, 0);
    ln_add_kernel<<<M2/8, 256>>>(s.t, w.g2, w.b2, x, xh);
}

extern "C" void kernel_launch(void* const* d_in, const int* in_sizes, int n_in,
                              void* d_out, int out_size)
{
    (void)in_sizes; (void)n_in; (void)out_size;
    const float* feat0 = (const float*)d_in[0];
    const float* feat1 = (const float*)d_in[1];
    const float* kp0   = (const float*)d_in[2];
    const float* kp1   = (const float*)d_in[3];
    maskp ms0 = (maskp)d_in[4];
    maskp ms1 = (maskp)d_in[5];
    maskp mc0 = (maskp)d_in[6];
    maskp mc1 = (maskp)d_in[7];
    const float* Wq = (const float*)d_in[8];
    const float* Wk = (const float*)d_in[9];
    const float* Wv = (const float*)d_in[10];
    const float* Wm = (const float*)d_in[11];
    const float* W1 = (const float*)d_in[12];
    const float* W2 = (const float*)d_in[13];
    const float* G1 = (const float*)d_in[14];
    const float* B1 = (const float*)d_in[15];
    const float* G2 = (const float*)d_in[16];
    const float* B2 = (const float*)d_in[17];

    cudaFuncSetAttribute(hgemm4_kernel,
                         cudaFuncAttributeMaxDynamicSharedMemorySize, DSMEM);

    float *px, *pq, *pin;
    __half *pxh;
    __half *whP, *whM, *wh1, *wh2;
    Bufs s;
    cudaGetSymbolAddress((void**)&px, g_x);
    cudaGetSymbolAddress((void**)&pxh, g_xh);
    cudaGetSymbolAddress((void**)&pq, g_qkv);
    cudaGetSymbolAddress((void**)&pin, g_invn);
    cudaGetSymbolAddress((void**)&s.t, g_tb);
    cudaGetSymbolAddress((void**)&s.kvks, g_kvks);
    cudaGetSymbolAddress((void**)&s.atth, g_atth);
    cudaGetSymbolAddress((void**)&s.msgh, g_msgh);
    cudaGetSymbolAddress((void**)&s.uh, g_uh);
    cudaGetSymbolAddress((void**)&whP, g_whP);
    cudaGetSymbolAddress((void**)&whM, g_whM);
    cudaGetSymbolAddress((void**)&wh1, g_wh1);
    cudaGetSymbolAddress((void**)&wh2, g_wh2);

    /* front-loaded weight prep + input round */
    wpackT_all_kernel<<<NL*CC*QS/256, 256>>>(Wq, Wk, Wv, whP);
    wtrans_all_kernel<<<NL*CC*CC/256, 256>>>(Wm, whM, CC, CC);
    wtrans_all_kernel<<<NL*C2*C2/256, 256>>>(W1, wh1, C2, C2);
    wtrans_all_kernel<<<NL*C2*CC/256, 256>>>(W2, wh2, C2, CC);
    split_in_kernel<<<M2*CC/256, 256>>>(feat0, feat1, px, pxh);

    for (int i = 0; i < 4; ++i) {
        LayerW w;
        w.g1 = G1 + (size_t)i * CC;
        w.b1 = B1 + (size_t)i * CC;
        w.g2 = G2 + (size_t)i * CC;
        w.b2 = B2 + (size_t)i * CC;
        w.whP = whP + (size_t)i * QS * CC;
        w.whM = whM + (size_t)i * CC * CC;
        w.wh1 = wh1 + (size_t)i * C2 * C2;
        w.wh2 = wh2 + (size_t)i * C2 * CC;

        hgemm4_kernel<<<dim3(6,128), 256, DSMEM>>>(
            pxh, (const __half*)0, w.whP, pq, (__half*)0, QS, CC, 0);

        if ((i & 1) == 0) {
            cudaMemsetAsync(s.kvks, 0, (size_t)(KVSZ + KSSZ) * sizeof(float), 0);
            self_kv_kernel<<<512, 256>>>(pq, ms0, ms1, s.kvks);
            self_att_kernel<<<M2/8, 256>>>(pq, s.kvks, s.atth);
        } else {
            invnorm_kernel<<<2*MD/8, 256>>>(px, kp0, kp1, pin);
            cross_att_kernel<<<M2/4, 256>>>(pq, kp0, kp1, pin, mc0, mc1, s.atth);
        }
        mlp_tail(px, pxh, w, s);
    }

    cudaMemcpyAsync(d_out, px, (size_t)M2 * CC * sizeof(float),
                    cudaMemcpyDeviceToDevice, 0);
}